// round 5
// baseline (speedup 1.0000x reference)
#include <cuda_runtime.h>
#include <cuda_bf16.h>

// ---------------------------------------------------------------------------
// GCN: h = relu(x@W1+b1); h = relu(gcnconv(h,Wc1,bc1)); h = relu(gcnconv(h,Wc2,bc2));
//      out = h@W2 + b2
// gcnconv(h,W,b): t = h@W; agg[i] = dinv[i]^2 * t[i] + sum_{e: col=i} norm[e]*t[row[e]];
//                 return agg + b
// norm[e] = dinv[row]*ew[e]*dinv[col];  deg[i] = 1 + sum_{e: col=i} ew[e]
//
// Hard-won target facts:
//  - v4/v2 fp32 atomics trap (cudaErrorInvalidAddressSpace). Scalar atomicAdd only.
//  - edge_index dtype is ambiguous (JAX x64 default-off may demote int64->int32).
//    We detect the encoding on-device and convert to int32 either way.
// ---------------------------------------------------------------------------

#define NN 100000
#define NE 1600000
#define FIN 256
#define HID 64
#define NCLS 40

// Scratch (allocation-free rule: __device__ globals)
__device__ float g_h[(size_t)NN * HID];
__device__ float g_t[(size_t)NN * HID];
__device__ float g_agg[(size_t)NN * HID];
__device__ float g_deg[NN];
__device__ float g_dinv[NN];
__device__ float g_norm[NE];
__device__ int   g_row32[NE];
__device__ int   g_col32[NE];
__device__ int   g_is32;   // 1 if edge_index buffer is int32, 0 if int64

// ---------------- dtype detection + index conversion ----------------

__global__ void flag_init_k(int* __restrict__ flag) {
    if (blockIdx.x == 0 && threadIdx.x == 0) *flag = 0;
}

// If buffer is little-endian int64 with values < 2^31, every odd 32-bit word
// is zero. If it is int32 edge data, odd words are node indices — over 64K
// samples at least one is nonzero with overwhelming probability.
__global__ void detect_k(const int* __restrict__ buf, int* __restrict__ flag) {
    int i = blockIdx.x * blockDim.x + threadIdx.x;   // 65536 threads
    if (buf[2 * i + 1] != 0) atomicOr(flag, 1);      // within rows region either way
}

// Materialize int32 row/col arrays for either encoding.
__global__ void cvt_idx_k(const int* __restrict__ buf,
                          const int* __restrict__ flag,
                          int* __restrict__ row32, int* __restrict__ col32) {
    int e = blockIdx.x * blockDim.x + threadIdx.x;
    if (e < NE) {
        if (*flag) {              // int32: [rows[NE] | cols[NE]]
            row32[e] = buf[e];
            col32[e] = buf[NE + e];
        } else {                  // int64: low words at even offsets
            row32[e] = buf[2 * e];
            col32[e] = buf[2 * NE + 2 * e];
        }
    }
}

// ---------------- degree / normalization ----------------

__global__ void deg_init_k(float* __restrict__ deg) {
    int i = blockIdx.x * blockDim.x + threadIdx.x;
    if (i < NN) deg[i] = 1.0f;  // self-loop weight
}

__global__ void deg_acc_k(const int* __restrict__ cols,
                          const float* __restrict__ ew,
                          float* __restrict__ deg) {
    int e = blockIdx.x * blockDim.x + threadIdx.x;
    if (e < NE) atomicAdd(&deg[cols[e]], ew[e]);
}

__global__ void dinv_k(const float* __restrict__ deg, float* __restrict__ dinv) {
    int i = blockIdx.x * blockDim.x + threadIdx.x;
    if (i < NN) {
        float d = deg[i];
        dinv[i] = (d > 0.0f) ? rsqrtf(d) : 0.0f;
    }
}

__global__ void norm_k(const int* __restrict__ rows,
                       const int* __restrict__ cols,
                       const float* __restrict__ ew,
                       const float* __restrict__ dinv,
                       float* __restrict__ nrm) {
    int e = blockIdx.x * blockDim.x + threadIdx.x;
    if (e < NE) nrm[e] = dinv[rows[e]] * ew[e] * dinv[cols[e]];
}

// ---------------- GEMM: [N,K] @ [K,64] -> [N,64] ----------------
// Block: 256 threads, tile 64 rows x 64 cols, 4x4 micro-tile per thread.

template <int K, bool RELU, bool BIAS>
__global__ void gemm_n64(const float* __restrict__ X, const float* __restrict__ W,
                         const float* __restrict__ bias, float* __restrict__ Y,
                         int N) {
    __shared__ float Xs[64][68];
    __shared__ float Ws[64][64];
    const int tid = threadIdx.x;
    const int row0 = blockIdx.x * 64;
    const int ty = tid >> 4;   // 0..15 -> row group
    const int tx = tid & 15;   // 0..15 -> col group

    float acc[4][4] = {};

    for (int kc = 0; kc < K; kc += 64) {
        // Stage X tile (64 rows x 64 k) as float4, coalesced
#pragma unroll
        for (int i = 0; i < 4; i++) {
            int idx = i * 256 + tid;    // float4 index 0..1023
            int r = idx >> 4;           // 16 float4 per row
            int k4 = idx & 15;
            float4 v = make_float4(0.f, 0.f, 0.f, 0.f);
            int rg = row0 + r;
            if (rg < N)
                v = *(const float4*)&X[(size_t)rg * K + kc + k4 * 4];
            *(float4*)&Xs[r][k4 * 4] = v;
        }
        // Stage W tile (64 k x 64 cols)
#pragma unroll
        for (int i = 0; i < 4; i++) {
            int idx = i * 256 + tid;
            int k = idx >> 4;
            int c4 = idx & 15;
            *(float4*)&Ws[k][c4 * 4] =
                *(const float4*)&W[(size_t)(kc + k) * 64 + c4 * 4];
        }
        __syncthreads();

#pragma unroll 16
        for (int k = 0; k < 64; k++) {
            float a0 = Xs[ty * 4 + 0][k];
            float a1 = Xs[ty * 4 + 1][k];
            float a2 = Xs[ty * 4 + 2][k];
            float a3 = Xs[ty * 4 + 3][k];
            float4 bv = *(float4*)&Ws[k][tx * 4];
            acc[0][0] += a0 * bv.x; acc[0][1] += a0 * bv.y;
            acc[0][2] += a0 * bv.z; acc[0][3] += a0 * bv.w;
            acc[1][0] += a1 * bv.x; acc[1][1] += a1 * bv.y;
            acc[1][2] += a1 * bv.z; acc[1][3] += a1 * bv.w;
            acc[2][0] += a2 * bv.x; acc[2][1] += a2 * bv.y;
            acc[2][2] += a2 * bv.z; acc[2][3] += a2 * bv.w;
            acc[3][0] += a3 * bv.x; acc[3][1] += a3 * bv.y;
            acc[3][2] += a3 * bv.z; acc[3][3] += a3 * bv.w;
        }
        __syncthreads();
    }

    float4 bb = make_float4(0.f, 0.f, 0.f, 0.f);
    if (BIAS) bb = *(const float4*)&bias[tx * 4];
#pragma unroll
    for (int i = 0; i < 4; i++) {
        int rg = row0 + ty * 4 + i;
        if (rg < N) {
            float4 o;
            o.x = acc[i][0]; o.y = acc[i][1]; o.z = acc[i][2]; o.w = acc[i][3];
            if (BIAS) { o.x += bb.x; o.y += bb.y; o.z += bb.z; o.w += bb.w; }
            if (RELU) {
                o.x = fmaxf(o.x, 0.f); o.y = fmaxf(o.y, 0.f);
                o.z = fmaxf(o.z, 0.f); o.w = fmaxf(o.w, 0.f);
            }
            *(float4*)&Y[(size_t)rg * 64 + tx * 4] = o;
        }
    }
}

// ---------------- final GEMM: [N,64] @ [64,40] + b ----------------

__global__ void gemm_final(const float* __restrict__ X, const float* __restrict__ W,
                           const float* __restrict__ bias, float* __restrict__ Y,
                           int N) {
    __shared__ float Xs[64][68];
    __shared__ float Ws[64][40];
    __shared__ float bs[40];
    const int tid = threadIdx.x;
    const int row0 = blockIdx.x * 64;

#pragma unroll
    for (int i = 0; i < 4; i++) {
        int idx = i * 256 + tid;
        int r = idx >> 4;
        int k4 = idx & 15;
        float4 v = make_float4(0.f, 0.f, 0.f, 0.f);
        int rg = row0 + r;
        if (rg < N) v = *(const float4*)&X[(size_t)rg * 64 + k4 * 4];
        *(float4*)&Xs[r][k4 * 4] = v;
    }
    for (int idx = tid; idx < 64 * 40; idx += 256)
        Ws[idx / 40][idx % 40] = W[idx];
    if (tid < 40) bs[tid] = bias[tid];
    __syncthreads();

#pragma unroll
    for (int i = 0; i < 10; i++) {
        int idx = tid + i * 256;   // 0..2559 = 64 rows x 40 cols
        int r = idx / 40;
        int c = idx % 40;
        float acc = bs[c];
#pragma unroll 16
        for (int k = 0; k < 64; k++) acc += Xs[r][k] * Ws[k][c];
        int rg = row0 + r;
        if (rg < N) Y[(size_t)rg * 40 + c] = acc;
    }
}

// ---------------- aggregation ----------------

// agg[i] = dinv[i]^2 * t[i]   (self-loop contribution; also initializes agg)
__global__ void agg_init_k(const float* __restrict__ t,
                           const float* __restrict__ dinv,
                           float* __restrict__ agg) {
    int id = blockIdx.x * blockDim.x + threadIdx.x;
    if (id < NN * 16) {
        int n = id >> 4;
        int c = id & 15;
        float di = dinv[n];
        float s = di * di;
        float4 v = *(const float4*)&t[(size_t)n * 64 + c * 4];
        v.x *= s; v.y *= s; v.z *= s; v.w *= s;
        *(float4*)&agg[(size_t)n * 64 + c * 4] = v;
    }
}

// agg[col[e]] += norm[e] * t[row[e]]   — thread per (edge, col), 64 lanes/edge.
// Warp covers 32 consecutive cols of one edge: coalesced gather (128B) and
// scalar atomics to 32 consecutive words (one L2 line, distinct addresses).
__global__ void edge_agg_k(const int* __restrict__ rows,
                           const int* __restrict__ cols,
                           const float* __restrict__ nrm,
                           const float* __restrict__ t,
                           float* __restrict__ agg) {
    long long id = (long long)blockIdx.x * blockDim.x + threadIdx.x;  // NE*64
    int e = (int)(id >> 6);
    int c = (int)(id & 63);
    if (e < NE) {
        int r = __ldg(&rows[e]);
        int d = __ldg(&cols[e]);
        float nv = __ldg(&nrm[e]);
        float v = __ldg(&t[(size_t)r * 64 + c]) * nv;
        atomicAdd(&agg[(size_t)d * 64 + c], v);
    }
}

// h[i] = relu(agg[i] + b)
__global__ void bias_relu_k(const float* __restrict__ agg,
                            const float* __restrict__ b,
                            float* __restrict__ h) {
    int id = blockIdx.x * blockDim.x + threadIdx.x;
    if (id < NN * 64) {
        int c = id & 63;
        h[id] = fmaxf(agg[id] + b[c], 0.0f);
    }
}

// ---------------- launch ----------------

extern "C" void kernel_launch(void* const* d_in, const int* in_sizes, int n_in,
                              void* d_out, int out_size) {
    const float* x   = (const float*)d_in[0];
    const int*   ei  = (const int*)d_in[1];     // raw words; encoding detected on-device
    const float* ew  = (const float*)d_in[2];
    const float* W1  = (const float*)d_in[3];
    const float* b1  = (const float*)d_in[4];
    const float* Wc1 = (const float*)d_in[5];
    const float* bc1 = (const float*)d_in[6];
    const float* Wc2 = (const float*)d_in[7];
    const float* bc2 = (const float*)d_in[8];
    const float* W2  = (const float*)d_in[9];
    const float* b2  = (const float*)d_in[10];
    float* out = (float*)d_out;

    float *h, *t, *agg, *deg, *dinv, *nrm;
    int *r32, *c32, *flag;
    cudaGetSymbolAddress((void**)&h,    g_h);
    cudaGetSymbolAddress((void**)&t,    g_t);
    cudaGetSymbolAddress((void**)&agg,  g_agg);
    cudaGetSymbolAddress((void**)&deg,  g_deg);
    cudaGetSymbolAddress((void**)&dinv, g_dinv);
    cudaGetSymbolAddress((void**)&nrm,  g_norm);
    cudaGetSymbolAddress((void**)&r32,  g_row32);
    cudaGetSymbolAddress((void**)&c32,  g_col32);
    cudaGetSymbolAddress((void**)&flag, g_is32);

    const int TB = 256;
    const int gemm_blocks = (NN + 63) / 64;  // 1563
    const long long edge_threads = (long long)NE * 64;
    const int edge_blocks = (int)((edge_threads + TB - 1) / TB);

    // index dtype detection + conversion
    flag_init_k<<<1, 32>>>(flag);
    detect_k<<<256, 256>>>(ei, flag);                       // 65536 samples
    cvt_idx_k<<<(NE + TB - 1) / TB, TB>>>(ei, flag, r32, c32);

    // normalization (shared by both convs)
    deg_init_k<<<(NN + TB - 1) / TB, TB>>>(deg);
    deg_acc_k<<<(NE + TB - 1) / TB, TB>>>(c32, ew, deg);
    dinv_k<<<(NN + TB - 1) / TB, TB>>>(deg, dinv);
    norm_k<<<(NE + TB - 1) / TB, TB>>>(r32, c32, ew, dinv, nrm);

    // h = relu(x @ W1 + b1)
    gemm_n64<FIN, true, true><<<gemm_blocks, TB>>>(x, W1, b1, h, NN);

    // conv1
    gemm_n64<HID, false, false><<<gemm_blocks, TB>>>(h, Wc1, nullptr, t, NN);
    agg_init_k<<<(NN * 16 + TB - 1) / TB, TB>>>(t, dinv, agg);
    edge_agg_k<<<edge_blocks, TB>>>(r32, c32, nrm, t, agg);
    bias_relu_k<<<(NN * 64 + TB - 1) / TB, TB>>>(agg, bc1, h);

    // conv2
    gemm_n64<HID, false, false><<<gemm_blocks, TB>>>(h, Wc2, nullptr, t, NN);
    agg_init_k<<<(NN * 16 + TB - 1) / TB, TB>>>(t, dinv, agg);
    edge_agg_k<<<edge_blocks, TB>>>(r32, c32, nrm, t, agg);
    bias_relu_k<<<(NN * 64 + TB - 1) / TB, TB>>>(agg, bc2, h);

    // out = h @ W2 + b2
    gemm_final<<<gemm_blocks, TB>>>(h, W2, b2, out, NN);
}

// round 8
// speedup vs baseline: 2.5056x; 2.5056x over previous
#include <cuda_runtime.h>
#include <cuda_bf16.h>

// ---------------------------------------------------------------------------
// GCN forward. Round 6: CSR-by-destination + warp-per-node segmented reduce
// replaces the atomicAdd edge scatter (was ~290us/conv, atomic-bound).
//
// Target facts learned:
//  - v4/v2 fp32 atomics trap on this target. Scalar atomicAdd only (and only
//    used for int counters / degree floats / CSR cursors now).
//  - edge_index encoding ambiguous (int32 vs int64) -> detected on device.
// ---------------------------------------------------------------------------

#define NN 100000
#define NE 1600000
#define FIN 256
#define HID 64
#define NCLS 40

// Scratch (__device__ globals; no allocations allowed)
__device__ float g_h[(size_t)NN * HID];
__device__ float g_t[(size_t)NN * HID];
__device__ float g_deg[NN];        // weighted degree (starts at 1 = self loop)
__device__ float g_dinv[NN];
__device__ int   g_row32[NE];
__device__ int   g_col32[NE];
__device__ int   g_cnt[NN];        // in-edge count per node
__device__ int   g_off[NN + 1];    // CSR offsets
__device__ int   g_cursor[NN];     // scatter cursors
__device__ int   g_bsum[128];      // block sums for scan
__device__ int   g_csr_src[NE];    // source node per CSR slot
__device__ float g_csr_w[NE];      // edge norm per CSR slot
__device__ int   g_is32;

// ---------------- dtype detection + conversion + degree count ----------------

__global__ void flag_init_k(int* __restrict__ flag) {
    if (blockIdx.x == 0 && threadIdx.x == 0) *flag = 0;
}

// int64 little-endian with small values => odd 32-bit words all zero.
__global__ void detect_k(const int* __restrict__ buf, int* __restrict__ flag) {
    int i = blockIdx.x * blockDim.x + threadIdx.x;   // 65536 samples
    if (buf[2 * i + 1] != 0) atomicOr(flag, 1);
}

__global__ void init_deg_k(float* __restrict__ deg, int* __restrict__ cnt) {
    int i = blockIdx.x * blockDim.x + threadIdx.x;
    if (i < NN) { deg[i] = 1.0f; cnt[i] = 0; }
}

// Convert indices, accumulate weighted degree and in-edge count.
__global__ void cvt_count_k(const int* __restrict__ buf,
                            const int* __restrict__ flag,
                            const float* __restrict__ ew,
                            int* __restrict__ row32, int* __restrict__ col32,
                            float* __restrict__ deg, int* __restrict__ cnt) {
    int e = blockIdx.x * blockDim.x + threadIdx.x;
    if (e < NE) {
        int r, c;
        if (*flag) { r = buf[e];     c = buf[NE + e]; }
        else       { r = buf[2 * e]; c = buf[2 * NE + 2 * e]; }
        row32[e] = r;
        col32[e] = c;
        atomicAdd(&deg[c], ew[e]);
        atomicAdd(&cnt[c], 1);
    }
}

__global__ void dinv_k(const float* __restrict__ deg, float* __restrict__ dinv) {
    int i = blockIdx.x * blockDim.x + threadIdx.x;
    if (i < NN) {
        float d = deg[i];
        dinv[i] = (d > 0.0f) ? rsqrtf(d) : 0.0f;
    }
}

// ---------------- exclusive scan of g_cnt -> g_off (3 kernels) ----------------
// scan1: 1024 elements/block (256 thr x 4), exclusive within block + block sum.

__global__ void scan1_k(const int* __restrict__ cnt, int* __restrict__ off,
                        int* __restrict__ bsum) {
    __shared__ int sh[256];
    int tid = threadIdx.x;
    int base = blockIdx.x * 1024 + tid * 4;
    int v[4];
#pragma unroll
    for (int j = 0; j < 4; j++) v[j] = (base + j < NN) ? cnt[base + j] : 0;
    int s = v[0] + v[1] + v[2] + v[3];
    sh[tid] = s;
    __syncthreads();
    // Hillis-Steele inclusive scan
    for (int d = 1; d < 256; d <<= 1) {
        int add = (tid >= d) ? sh[tid - d] : 0;
        __syncthreads();
        sh[tid] += add;
        __syncthreads();
    }
    int p = sh[tid] - s;   // exclusive prefix of this thread's group
    int run = p;
#pragma unroll
    for (int j = 0; j < 4; j++) {
        if (base + j < NN) off[base + j] = run;
        run += v[j];
    }
    if (tid == 255) bsum[blockIdx.x] = sh[255];
}

// scan2: single block scans the 98 block sums (exclusive), sets off[NN]=NE.
__global__ void scan2_k(int* __restrict__ bsum, int* __restrict__ off, int nblk) {
    __shared__ int sh[128];
    int tid = threadIdx.x;
    int s = (tid < nblk) ? bsum[tid] : 0;
    sh[tid] = s;
    __syncthreads();
    for (int d = 1; d < 128; d <<= 1) {
        int add = (tid >= d) ? sh[tid - d] : 0;
        __syncthreads();
        sh[tid] += add;
        __syncthreads();
    }
    if (tid < nblk) bsum[tid] = sh[tid] - s;   // exclusive
    if (tid == 0) off[NN] = NE;
}

// scan3: add block offsets; initialize cursors.
__global__ void scan3_k(int* __restrict__ off, const int* __restrict__ bsum,
                        int* __restrict__ cursor) {
    int i = blockIdx.x * blockDim.x + threadIdx.x;
    if (i < NN) {
        int o = off[i] + bsum[i >> 10];
        off[i] = o;
        cursor[i] = o;
    }
}

// scatter edges into CSR, computing norm inline.
__global__ void scatter_k(const int* __restrict__ row32, const int* __restrict__ col32,
                          const float* __restrict__ ew, const float* __restrict__ dinv,
                          int* __restrict__ cursor,
                          int* __restrict__ csr_src, float* __restrict__ csr_w) {
    int e = blockIdx.x * blockDim.x + threadIdx.x;
    if (e < NE) {
        int r = row32[e];
        int c = col32[e];
        float w = dinv[r] * ew[e] * dinv[c];
        int pos = atomicAdd(&cursor[c], 1);
        csr_src[pos] = r;
        csr_w[pos] = w;
    }
}

// ---------------- GEMM: [N,K] @ [K,64] -> [N,64] ----------------

template <int K, bool RELU, bool BIAS>
__global__ void gemm_n64(const float* __restrict__ X, const float* __restrict__ W,
                         const float* __restrict__ bias, float* __restrict__ Y,
                         int N) {
    __shared__ float Xs[64][68];
    __shared__ float Ws[64][64];
    const int tid = threadIdx.x;
    const int row0 = blockIdx.x * 64;
    const int ty = tid >> 4;
    const int tx = tid & 15;

    float acc[4][4] = {};

    for (int kc = 0; kc < K; kc += 64) {
#pragma unroll
        for (int i = 0; i < 4; i++) {
            int idx = i * 256 + tid;
            int r = idx >> 4;
            int k4 = idx & 15;
            float4 v = make_float4(0.f, 0.f, 0.f, 0.f);
            int rg = row0 + r;
            if (rg < N)
                v = *(const float4*)&X[(size_t)rg * K + kc + k4 * 4];
            *(float4*)&Xs[r][k4 * 4] = v;
        }
#pragma unroll
        for (int i = 0; i < 4; i++) {
            int idx = i * 256 + tid;
            int k = idx >> 4;
            int c4 = idx & 15;
            *(float4*)&Ws[k][c4 * 4] =
                *(const float4*)&W[(size_t)(kc + k) * 64 + c4 * 4];
        }
        __syncthreads();

#pragma unroll 16
        for (int k = 0; k < 64; k++) {
            float a0 = Xs[ty * 4 + 0][k];
            float a1 = Xs[ty * 4 + 1][k];
            float a2 = Xs[ty * 4 + 2][k];
            float a3 = Xs[ty * 4 + 3][k];
            float4 bv = *(float4*)&Ws[k][tx * 4];
            acc[0][0] += a0 * bv.x; acc[0][1] += a0 * bv.y;
            acc[0][2] += a0 * bv.z; acc[0][3] += a0 * bv.w;
            acc[1][0] += a1 * bv.x; acc[1][1] += a1 * bv.y;
            acc[1][2] += a1 * bv.z; acc[1][3] += a1 * bv.w;
            acc[2][0] += a2 * bv.x; acc[2][1] += a2 * bv.y;
            acc[2][2] += a2 * bv.z; acc[2][3] += a2 * bv.w;
            acc[3][0] += a3 * bv.x; acc[3][1] += a3 * bv.y;
            acc[3][2] += a3 * bv.z; acc[3][3] += a3 * bv.w;
        }
        __syncthreads();
    }

    float4 bb = make_float4(0.f, 0.f, 0.f, 0.f);
    if (BIAS) bb = *(const float4*)&bias[tx * 4];
#pragma unroll
    for (int i = 0; i < 4; i++) {
        int rg = row0 + ty * 4 + i;
        if (rg < N) {
            float4 o;
            o.x = acc[i][0]; o.y = acc[i][1]; o.z = acc[i][2]; o.w = acc[i][3];
            if (BIAS) { o.x += bb.x; o.y += bb.y; o.z += bb.z; o.w += bb.w; }
            if (RELU) {
                o.x = fmaxf(o.x, 0.f); o.y = fmaxf(o.y, 0.f);
                o.z = fmaxf(o.z, 0.f); o.w = fmaxf(o.w, 0.f);
            }
            *(float4*)&Y[(size_t)rg * 64 + tx * 4] = o;
        }
    }
}

// ---------------- final GEMM: [N,64] @ [64,40] + b ----------------

__global__ void gemm_final(const float* __restrict__ X, const float* __restrict__ W,
                           const float* __restrict__ bias, float* __restrict__ Y,
                           int N) {
    __shared__ float Xs[64][68];
    __shared__ float Ws[64][40];
    __shared__ float bs[40];
    const int tid = threadIdx.x;
    const int row0 = blockIdx.x * 64;

#pragma unroll
    for (int i = 0; i < 4; i++) {
        int idx = i * 256 + tid;
        int r = idx >> 4;
        int k4 = idx & 15;
        float4 v = make_float4(0.f, 0.f, 0.f, 0.f);
        int rg = row0 + r;
        if (rg < N) v = *(const float4*)&X[(size_t)rg * 64 + k4 * 4];
        *(float4*)&Xs[r][k4 * 4] = v;
    }
    for (int idx = tid; idx < 64 * 40; idx += 256)
        Ws[idx / 40][idx % 40] = W[idx];
    if (tid < 40) bs[tid] = bias[tid];
    __syncthreads();

#pragma unroll
    for (int i = 0; i < 10; i++) {
        int idx = tid + i * 256;
        int r = idx / 40;
        int c = idx % 40;
        float acc = bs[c];
#pragma unroll 16
        for (int k = 0; k < 64; k++) acc += Xs[r][k] * Ws[k][c];
        int rg = row0 + r;
        if (rg < N) Y[(size_t)rg * 40 + c] = acc;
    }
}

// ---------------- fused CSR aggregation + bias + relu ----------------
// Warp per node. lane handles cols {2*lane, 2*lane+1} as float2.
// h[n] = relu( dinv[n]^2 * t[n] + sum_e w[e]*t[src[e]] + bias )

__global__ void spmm_csr_k(const int* __restrict__ off,
                           const int* __restrict__ src,
                           const float* __restrict__ wt,
                           const float* __restrict__ t,
                           const float* __restrict__ dinv,
                           const float* __restrict__ bias,
                           float* __restrict__ hout) {
    int n = blockIdx.x * 8 + (threadIdx.x >> 5);
    if (n >= NN) return;
    int lane = threadIdx.x & 31;
    const float2* t2 = (const float2*)t;

    float di = __ldg(&dinv[n]);
    float sw = di * di;
    float2 self = t2[(size_t)n * 32 + lane];
    float accx = self.x * sw;
    float accy = self.y * sw;

    int e = __ldg(&off[n]);
    const int end = __ldg(&off[n + 1]);

    // 4-way unroll: batch independent gathers (MLP=4) to hide L2 latency.
    for (; e + 4 <= end; e += 4) {
        int s0 = __ldg(&src[e + 0]);
        int s1 = __ldg(&src[e + 1]);
        int s2 = __ldg(&src[e + 2]);
        int s3 = __ldg(&src[e + 3]);
        float w0 = __ldg(&wt[e + 0]);
        float w1 = __ldg(&wt[e + 1]);
        float w2 = __ldg(&wt[e + 2]);
        float w3 = __ldg(&wt[e + 3]);
        float2 v0 = t2[(size_t)s0 * 32 + lane];
        float2 v1 = t2[(size_t)s1 * 32 + lane];
        float2 v2 = t2[(size_t)s2 * 32 + lane];
        float2 v3 = t2[(size_t)s3 * 32 + lane];
        accx += w0 * v0.x + w1 * v1.x + w2 * v2.x + w3 * v3.x;
        accy += w0 * v0.y + w1 * v1.y + w2 * v2.y + w3 * v3.y;
    }
    for (; e < end; e++) {
        int s = __ldg(&src[e]);
        float w = __ldg(&wt[e]);
        float2 v = t2[(size_t)s * 32 + lane];
        accx += w * v.x;
        accy += w * v.y;
    }

    float2 bv = ((const float2*)bias)[lane];
    accx = fmaxf(accx + bv.x, 0.0f);
    accy = fmaxf(accy + bv.y, 0.0f);
    float2 o; o.x = accx; o.y = accy;
    ((float2*)hout)[(size_t)n * 32 + lane] = o;
}

// ---------------- launch ----------------

extern "C" void kernel_launch(void* const* d_in, const int* in_sizes, int n_in,
                              void* d_out, int out_size) {
    const float* x   = (const float*)d_in[0];
    const int*   ei  = (const int*)d_in[1];
    const float* ew  = (const float*)d_in[2];
    const float* W1  = (const float*)d_in[3];
    const float* b1  = (const float*)d_in[4];
    const float* Wc1 = (const float*)d_in[5];
    const float* bc1 = (const float*)d_in[6];
    const float* Wc2 = (const float*)d_in[7];
    const float* bc2 = (const float*)d_in[8];
    const float* W2  = (const float*)d_in[9];
    const float* b2  = (const float*)d_in[10];
    float* out = (float*)d_out;

    float *h, *t, *deg, *dinv, *cw;
    int *r32, *c32, *flag, *cnt, *off, *cursor, *bsum, *csrc;
    cudaGetSymbolAddress((void**)&h,     g_h);
    cudaGetSymbolAddress((void**)&t,     g_t);
    cudaGetSymbolAddress((void**)&deg,   g_deg);
    cudaGetSymbolAddress((void**)&dinv,  g_dinv);
    cudaGetSymbolAddress((void**)&r32,   g_row32);
    cudaGetSymbolAddress((void**)&c32,   g_col32);
    cudaGetSymbolAddress((void**)&flag,  g_is32);
    cudaGetSymbolAddress((void**)&cnt,   g_cnt);
    cudaGetSymbolAddress((void**)&off,   g_off);
    cudaGetSymbolAddress((void**)&cursor,g_cursor);
    cudaGetSymbolAddress((void**)&bsum,  g_bsum);
    cudaGetSymbolAddress((void**)&csrc,  g_csr_src);
    cudaGetSymbolAddress((void**)&cw,    g_csr_w);

    const int TB = 256;
    const int gemm_blocks = (NN + 63) / 64;        // 1563
    const int nscan = (NN + 1023) / 1024;          // 98
    const int spmm_blocks = (NN + 7) / 8;          // 12500

    // index dtype detection + conversion + degree/count
    flag_init_k<<<1, 32>>>(flag);
    detect_k<<<256, 256>>>(ei, flag);
    init_deg_k<<<(NN + TB - 1) / TB, TB>>>(deg, cnt);
    cvt_count_k<<<(NE + TB - 1) / TB, TB>>>(ei, flag, ew, r32, c32, deg, cnt);
    dinv_k<<<(NN + TB - 1) / TB, TB>>>(deg, dinv);

    // CSR build
    scan1_k<<<nscan, 256>>>(cnt, off, bsum);
    scan2_k<<<1, 128>>>(bsum, off, nscan);
    scan3_k<<<(NN + TB - 1) / TB, TB>>>(off, bsum, cursor);
    scatter_k<<<(NE + TB - 1) / TB, TB>>>(r32, c32, ew, dinv, cursor, csrc, cw);

    // h = relu(x @ W1 + b1)
    gemm_n64<FIN, true, true><<<gemm_blocks, TB>>>(x, W1, b1, h, NN);

    // conv1: t = h@Wc1 ; h = relu(S t + bc1)
    gemm_n64<HID, false, false><<<gemm_blocks, TB>>>(h, Wc1, nullptr, t, NN);
    spmm_csr_k<<<spmm_blocks, TB>>>(off, csrc, cw, t, dinv, bc1, h);

    // conv2
    gemm_n64<HID, false, false><<<gemm_blocks, TB>>>(h, Wc2, nullptr, t, NN);
    spmm_csr_k<<<spmm_blocks, TB>>>(off, csrc, cw, t, dinv, bc2, h);

    // out = h @ W2 + b2
    gemm_final<<<gemm_blocks, TB>>>(h, W2, b2, out, NN);
}

// round 9
// speedup vs baseline: 2.7658x; 1.1039x over previous
#include <cuda_runtime.h>
#include <cuda_bf16.h>
#include <cstdint>

// ---------------------------------------------------------------------------
// GCN forward. Round 8: TF32 mma.sync tensor-core GEMMs (M128xN64 tiles)
// replace the fp32 FFMA GEMMs (were ~215us combined, FFMA-roofline-bound).
// CSR spmm + preprocessing unchanged from the 344.8us Round-6 kernel.
//
// Target facts learned:
//  - v4/v2 fp32 atomics trap. Scalar atomicAdd only.
//  - edge_index encoding ambiguous (int32 vs int64) -> detected on device.
// ---------------------------------------------------------------------------

#define NN 100000
#define NE 1600000
#define FIN 256
#define HID 64
#define NCLS 40

// Scratch (__device__ globals; no allocations allowed)
__device__ float g_h[(size_t)NN * HID];
__device__ float g_t[(size_t)NN * HID];
__device__ float g_deg[NN];
__device__ float g_dinv[NN];
__device__ int   g_row32[NE];
__device__ int   g_col32[NE];
__device__ int   g_cnt[NN];
__device__ int   g_off[NN + 1];
__device__ int   g_cursor[NN];
__device__ int   g_bsum[128];
__device__ int   g_csr_src[NE];
__device__ float g_csr_w[NE];
__device__ int   g_is32;

__device__ __forceinline__ float to_tf32(float x) {
    uint32_t u;
    asm("cvt.rna.tf32.f32 %0, %1;" : "=r"(u) : "f"(x));
    return __uint_as_float(u);
}

// ---------------- dtype detection + conversion + degree count ----------------

__global__ void flag_init_k(int* __restrict__ flag) {
    if (blockIdx.x == 0 && threadIdx.x == 0) *flag = 0;
}

__global__ void detect_k(const int* __restrict__ buf, int* __restrict__ flag) {
    int i = blockIdx.x * blockDim.x + threadIdx.x;   // 65536 samples
    if (buf[2 * i + 1] != 0) atomicOr(flag, 1);
}

__global__ void init_deg_k(float* __restrict__ deg, int* __restrict__ cnt) {
    int i = blockIdx.x * blockDim.x + threadIdx.x;
    if (i < NN) { deg[i] = 1.0f; cnt[i] = 0; }
}

__global__ void cvt_count_k(const int* __restrict__ buf,
                            const int* __restrict__ flag,
                            const float* __restrict__ ew,
                            int* __restrict__ row32, int* __restrict__ col32,
                            float* __restrict__ deg, int* __restrict__ cnt) {
    int e = blockIdx.x * blockDim.x + threadIdx.x;
    if (e < NE) {
        int r, c;
        if (*flag) { r = buf[e];     c = buf[NE + e]; }
        else       { r = buf[2 * e]; c = buf[2 * NE + 2 * e]; }
        row32[e] = r;
        col32[e] = c;
        atomicAdd(&deg[c], ew[e]);
        atomicAdd(&cnt[c], 1);
    }
}

__global__ void dinv_k(const float* __restrict__ deg, float* __restrict__ dinv) {
    int i = blockIdx.x * blockDim.x + threadIdx.x;
    if (i < NN) {
        float d = deg[i];
        dinv[i] = (d > 0.0f) ? rsqrtf(d) : 0.0f;
    }
}

// ---------------- exclusive scan (3 kernels) ----------------

__global__ void scan1_k(const int* __restrict__ cnt, int* __restrict__ off,
                        int* __restrict__ bsum) {
    __shared__ int sh[256];
    int tid = threadIdx.x;
    int base = blockIdx.x * 1024 + tid * 4;
    int v[4];
#pragma unroll
    for (int j = 0; j < 4; j++) v[j] = (base + j < NN) ? cnt[base + j] : 0;
    int s = v[0] + v[1] + v[2] + v[3];
    sh[tid] = s;
    __syncthreads();
    for (int d = 1; d < 256; d <<= 1) {
        int add = (tid >= d) ? sh[tid - d] : 0;
        __syncthreads();
        sh[tid] += add;
        __syncthreads();
    }
    int run = sh[tid] - s;
#pragma unroll
    for (int j = 0; j < 4; j++) {
        if (base + j < NN) off[base + j] = run;
        run += v[j];
    }
    if (tid == 255) bsum[blockIdx.x] = sh[255];
}

__global__ void scan2_k(int* __restrict__ bsum, int* __restrict__ off, int nblk) {
    __shared__ int sh[128];
    int tid = threadIdx.x;
    int s = (tid < nblk) ? bsum[tid] : 0;
    sh[tid] = s;
    __syncthreads();
    for (int d = 1; d < 128; d <<= 1) {
        int add = (tid >= d) ? sh[tid - d] : 0;
        __syncthreads();
        sh[tid] += add;
        __syncthreads();
    }
    if (tid < nblk) bsum[tid] = sh[tid] - s;
    if (tid == 0) off[NN] = NE;
}

__global__ void scan3_k(int* __restrict__ off, const int* __restrict__ bsum,
                        int* __restrict__ cursor) {
    int i = blockIdx.x * blockDim.x + threadIdx.x;
    if (i < NN) {
        int o = off[i] + bsum[i >> 10];
        off[i] = o;
        cursor[i] = o;
    }
}

__global__ void scatter_k(const int* __restrict__ row32, const int* __restrict__ col32,
                          const float* __restrict__ ew, const float* __restrict__ dinv,
                          int* __restrict__ cursor,
                          int* __restrict__ csr_src, float* __restrict__ csr_w) {
    int e = blockIdx.x * blockDim.x + threadIdx.x;
    if (e < NE) {
        int r = row32[e];
        int c = col32[e];
        float w = dinv[r] * ew[e] * dinv[c];
        int pos = atomicAdd(&cursor[c], 1);
        csr_src[pos] = r;
        csr_w[pos] = w;
    }
}

// ---------------- TF32 GEMM: [N,K] @ [K,64] -> [N,64] ----------------
// Block 256 thr (8 warps). Tile 128x64. Warp computes 16 rows x 64 cols via
// 8x mma.m16n8k8 per k8-step. Inputs rounded to tf32 at staging; fp32 accum.

template <int K, bool RELU, bool BIAS>
__global__ void gemm_tf32(const float* __restrict__ X, const float* __restrict__ W,
                          const float* __restrict__ bias, float* __restrict__ Y,
                          int N) {
    constexpr int KC = 32;
    __shared__ float Xs[128][36];   // pad 4: conflict-free frag loads
    __shared__ float Ws[32][68];    // pad 4
    const int tid = threadIdx.x;
    const int wid = tid >> 5;
    const int lane = tid & 31;
    const int g = lane >> 2;        // 0..7
    const int tg = lane & 3;        // 0..3
    const int row0 = blockIdx.x * 128;
    const int wm = wid * 16;

    float c[8][4];
#pragma unroll
    for (int nt = 0; nt < 8; nt++)
#pragma unroll
        for (int j = 0; j < 4; j++) c[nt][j] = 0.0f;

    for (int kc = 0; kc < K; kc += KC) {
        // Stage X tile (128 rows x 32 k) as float4, tf32-rounded
#pragma unroll
        for (int i = 0; i < 4; i++) {
            int idx = i * 256 + tid;     // 1024 float4
            int r = idx >> 3;            // 8 float4 per row
            int k4 = idx & 7;
            float4 v = make_float4(0.f, 0.f, 0.f, 0.f);
            int rg = row0 + r;
            if (rg < N)
                v = *(const float4*)&X[(size_t)rg * K + kc + k4 * 4];
            Xs[r][k4 * 4 + 0] = to_tf32(v.x);
            Xs[r][k4 * 4 + 1] = to_tf32(v.y);
            Xs[r][k4 * 4 + 2] = to_tf32(v.z);
            Xs[r][k4 * 4 + 3] = to_tf32(v.w);
        }
        // Stage W tile (32 k x 64 cols)
#pragma unroll
        for (int i = 0; i < 2; i++) {
            int idx = i * 256 + tid;     // 512 float4
            int k = idx >> 4;            // 16 float4 per row
            int c4 = idx & 15;
            float4 v = *(const float4*)&W[(size_t)(kc + k) * 64 + c4 * 4];
            Ws[k][c4 * 4 + 0] = to_tf32(v.x);
            Ws[k][c4 * 4 + 1] = to_tf32(v.y);
            Ws[k][c4 * 4 + 2] = to_tf32(v.z);
            Ws[k][c4 * 4 + 3] = to_tf32(v.w);
        }
        __syncthreads();

#pragma unroll
        for (int k8 = 0; k8 < KC; k8 += 8) {
            uint32_t a0 = __float_as_uint(Xs[wm + g][k8 + tg]);
            uint32_t a1 = __float_as_uint(Xs[wm + g + 8][k8 + tg]);
            uint32_t a2 = __float_as_uint(Xs[wm + g][k8 + tg + 4]);
            uint32_t a3 = __float_as_uint(Xs[wm + g + 8][k8 + tg + 4]);
#pragma unroll
            for (int nt = 0; nt < 8; nt++) {
                uint32_t b0 = __float_as_uint(Ws[k8 + tg][nt * 8 + g]);
                uint32_t b1 = __float_as_uint(Ws[k8 + tg + 4][nt * 8 + g]);
                asm volatile(
                    "mma.sync.aligned.m16n8k8.row.col.f32.tf32.tf32.f32 "
                    "{%0,%1,%2,%3}, {%4,%5,%6,%7}, {%8,%9}, {%0,%1,%2,%3};"
                    : "+f"(c[nt][0]), "+f"(c[nt][1]), "+f"(c[nt][2]), "+f"(c[nt][3])
                    : "r"(a0), "r"(a1), "r"(a2), "r"(a3), "r"(b0), "r"(b1));
            }
        }
        __syncthreads();
    }

    // Epilogue: thread owns rows (wm+g, wm+g+8), cols nt*8 + 2*tg (+1)
    const int r0 = row0 + wm + g;
    const int r1 = r0 + 8;
#pragma unroll
    for (int nt = 0; nt < 8; nt++) {
        int n0 = nt * 8 + 2 * tg;
        float bx = 0.f, by = 0.f;
        if (BIAS) { bx = __ldg(&bias[n0]); by = __ldg(&bias[n0 + 1]); }
        float2 v0, v1;
        v0.x = c[nt][0] + bx; v0.y = c[nt][1] + by;
        v1.x = c[nt][2] + bx; v1.y = c[nt][3] + by;
        if (RELU) {
            v0.x = fmaxf(v0.x, 0.f); v0.y = fmaxf(v0.y, 0.f);
            v1.x = fmaxf(v1.x, 0.f); v1.y = fmaxf(v1.y, 0.f);
        }
        if (r0 < N) *(float2*)&Y[(size_t)r0 * 64 + n0] = v0;
        if (r1 < N) *(float2*)&Y[(size_t)r1 * 64 + n0] = v1;
    }
}

// ---------------- final GEMM: [N,64] @ [64,40] + b (fp32) ----------------

__global__ void gemm_final(const float* __restrict__ X, const float* __restrict__ W,
                           const float* __restrict__ bias, float* __restrict__ Y,
                           int N) {
    __shared__ float Xs[64][68];
    __shared__ float Ws[64][40];
    __shared__ float bs[40];
    const int tid = threadIdx.x;
    const int row0 = blockIdx.x * 64;

#pragma unroll
    for (int i = 0; i < 4; i++) {
        int idx = i * 256 + tid;
        int r = idx >> 4;
        int k4 = idx & 15;
        float4 v = make_float4(0.f, 0.f, 0.f, 0.f);
        int rg = row0 + r;
        if (rg < N) v = *(const float4*)&X[(size_t)rg * 64 + k4 * 4];
        *(float4*)&Xs[r][k4 * 4] = v;
    }
    for (int idx = tid; idx < 64 * 40; idx += 256)
        Ws[idx / 40][idx % 40] = W[idx];
    if (tid < 40) bs[tid] = bias[tid];
    __syncthreads();

#pragma unroll
    for (int i = 0; i < 10; i++) {
        int idx = tid + i * 256;
        int r = idx / 40;
        int c = idx % 40;
        float acc = bs[c];
#pragma unroll 16
        for (int k = 0; k < 64; k++) acc += Xs[r][k] * Ws[k][c];
        int rg = row0 + r;
        if (rg < N) Y[(size_t)rg * 40 + c] = acc;
    }
}

// ---------------- fused CSR aggregation + bias + relu ----------------

__global__ void spmm_csr_k(const int* __restrict__ off,
                           const int* __restrict__ src,
                           const float* __restrict__ wt,
                           const float* __restrict__ t,
                           const float* __restrict__ dinv,
                           const float* __restrict__ bias,
                           float* __restrict__ hout) {
    int n = blockIdx.x * 8 + (threadIdx.x >> 5);
    if (n >= NN) return;
    int lane = threadIdx.x & 31;
    const float2* t2 = (const float2*)t;

    float di = __ldg(&dinv[n]);
    float sw = di * di;
    float2 self = t2[(size_t)n * 32 + lane];
    float accx = self.x * sw;
    float accy = self.y * sw;

    int e = __ldg(&off[n]);
    const int end = __ldg(&off[n + 1]);

    for (; e + 4 <= end; e += 4) {
        int s0 = __ldg(&src[e + 0]);
        int s1 = __ldg(&src[e + 1]);
        int s2 = __ldg(&src[e + 2]);
        int s3 = __ldg(&src[e + 3]);
        float w0 = __ldg(&wt[e + 0]);
        float w1 = __ldg(&wt[e + 1]);
        float w2 = __ldg(&wt[e + 2]);
        float w3 = __ldg(&wt[e + 3]);
        float2 v0 = t2[(size_t)s0 * 32 + lane];
        float2 v1 = t2[(size_t)s1 * 32 + lane];
        float2 v2 = t2[(size_t)s2 * 32 + lane];
        float2 v3 = t2[(size_t)s3 * 32 + lane];
        accx += w0 * v0.x + w1 * v1.x + w2 * v2.x + w3 * v3.x;
        accy += w0 * v0.y + w1 * v1.y + w2 * v2.y + w3 * v3.y;
    }
    for (; e < end; e++) {
        int s = __ldg(&src[e]);
        float w = __ldg(&wt[e]);
        float2 v = t2[(size_t)s * 32 + lane];
        accx += w * v.x;
        accy += w * v.y;
    }

    float2 bv = ((const float2*)bias)[lane];
    accx = fmaxf(accx + bv.x, 0.0f);
    accy = fmaxf(accy + bv.y, 0.0f);
    float2 o; o.x = accx; o.y = accy;
    ((float2*)hout)[(size_t)n * 32 + lane] = o;
}

// ---------------- launch ----------------

extern "C" void kernel_launch(void* const* d_in, const int* in_sizes, int n_in,
                              void* d_out, int out_size) {
    const float* x   = (const float*)d_in[0];
    const int*   ei  = (const int*)d_in[1];
    const float* ew  = (const float*)d_in[2];
    const float* W1  = (const float*)d_in[3];
    const float* b1  = (const float*)d_in[4];
    const float* Wc1 = (const float*)d_in[5];
    const float* bc1 = (const float*)d_in[6];
    const float* Wc2 = (const float*)d_in[7];
    const float* bc2 = (const float*)d_in[8];
    const float* W2  = (const float*)d_in[9];
    const float* b2  = (const float*)d_in[10];
    float* out = (float*)d_out;

    float *h, *t, *deg, *dinv, *cw;
    int *r32, *c32, *flag, *cnt, *off, *cursor, *bsum, *csrc;
    cudaGetSymbolAddress((void**)&h,     g_h);
    cudaGetSymbolAddress((void**)&t,     g_t);
    cudaGetSymbolAddress((void**)&deg,   g_deg);
    cudaGetSymbolAddress((void**)&dinv,  g_dinv);
    cudaGetSymbolAddress((void**)&r32,   g_row32);
    cudaGetSymbolAddress((void**)&c32,   g_col32);
    cudaGetSymbolAddress((void**)&flag,  g_is32);
    cudaGetSymbolAddress((void**)&cnt,   g_cnt);
    cudaGetSymbolAddress((void**)&off,   g_off);
    cudaGetSymbolAddress((void**)&cursor,g_cursor);
    cudaGetSymbolAddress((void**)&bsum,  g_bsum);
    cudaGetSymbolAddress((void**)&csrc,  g_csr_src);
    cudaGetSymbolAddress((void**)&cw,    g_csr_w);

    const int TB = 256;
    const int mma_blocks = (NN + 127) / 128;       // 782
    const int fin_blocks = (NN + 63) / 64;         // 1563
    const int nscan = (NN + 1023) / 1024;          // 98
    const int spmm_blocks = (NN + 7) / 8;          // 12500

    // index dtype detection + conversion + degree/count
    flag_init_k<<<1, 32>>>(flag);
    detect_k<<<256, 256>>>(ei, flag);
    init_deg_k<<<(NN + TB - 1) / TB, TB>>>(deg, cnt);
    cvt_count_k<<<(NE + TB - 1) / TB, TB>>>(ei, flag, ew, r32, c32, deg, cnt);
    dinv_k<<<(NN + TB - 1) / TB, TB>>>(deg, dinv);

    // CSR build
    scan1_k<<<nscan, 256>>>(cnt, off, bsum);
    scan2_k<<<1, 128>>>(bsum, off, nscan);
    scan3_k<<<(NN + TB - 1) / TB, TB>>>(off, bsum, cursor);
    scatter_k<<<(NE + TB - 1) / TB, TB>>>(r32, c32, ew, dinv, cursor, csrc, cw);

    // h = relu(x @ W1 + b1)
    gemm_tf32<FIN, true, true><<<mma_blocks, TB>>>(x, W1, b1, h, NN);

    // conv1: t = h@Wc1 ; h = relu(S t + bc1)
    gemm_tf32<HID, false, false><<<mma_blocks, TB>>>(h, Wc1, nullptr, t, NN);
    spmm_csr_k<<<spmm_blocks, TB>>>(off, csrc, cw, t, dinv, bc1, h);

    // conv2
    gemm_tf32<HID, false, false><<<mma_blocks, TB>>>(h, Wc2, nullptr, t, NN);
    spmm_csr_k<<<spmm_blocks, TB>>>(off, csrc, cw, t, dinv, bc2, h);

    // out = h @ W2 + b2
    gemm_final<<<fin_blocks, TB>>>(h, W2, b2, out, NN);
}

// round 10
// speedup vs baseline: 2.9089x; 1.0517x over previous
#include <cuda_runtime.h>
#include <cuda_bf16.h>
#include <cstdint>

// ---------------------------------------------------------------------------
// GCN forward. Round 9: launch fusion (16->13), packed CSR (int2), 8-way
// unrolled spmm, gemm1 hoisted to the ncu-captured launch slot.
//
// Target facts learned:
//  - v4/v2 fp32 atomics trap. Scalar atomicAdd only. (Plain vector loads OK.)
//  - edge_index encoding ambiguous (int32 vs int64) -> detected on device.
//  - ~3us per-launch floor: fewer, fatter kernels.
// ---------------------------------------------------------------------------

#define NN 100000
#define NE 1600000
#define FIN 256
#define HID 64
#define NCLS 40

// Scratch (__device__ globals; no allocations allowed)
__device__ float g_h[(size_t)NN * HID];
__device__ float g_t[(size_t)NN * HID];
__device__ float g_deg[NN];
__device__ float g_dinv[NN];
__device__ int   g_row32[NE];
__device__ int   g_col32[NE];
__device__ int   g_cnt[NN];
__device__ int   g_off[NN + 1];
__device__ int   g_cursor[NN];
__device__ int   g_bsum[128];
__device__ int2  g_csr[NE];        // packed {src, float_as_int(w)}
__device__ int   g_is32;

__device__ __forceinline__ float to_tf32(float x) {
    uint32_t u;
    asm("cvt.rna.tf32.f32 %0, %1;" : "=r"(u) : "f"(x));
    return __uint_as_float(u);
}

// ---------------- init + dtype detection + conversion/count ----------------

// deg=1 (self loop), cnt=0, flag=0 — one kernel.
__global__ void init_k(float* __restrict__ deg, int* __restrict__ cnt,
                       int* __restrict__ flag) {
    int i = blockIdx.x * blockDim.x + threadIdx.x;
    if (i < NN) { deg[i] = 1.0f; cnt[i] = 0; }
    if (i == 0) *flag = 0;
}

// int64 little-endian with small values => odd 32-bit words all zero.
__global__ void detect_k(const int* __restrict__ buf, int* __restrict__ flag) {
    int i = blockIdx.x * blockDim.x + threadIdx.x;   // 65536 samples
    if (buf[2 * i + 1] != 0) atomicOr(flag, 1);
}

__global__ void cvt_count_k(const int* __restrict__ buf,
                            const int* __restrict__ flag,
                            const float* __restrict__ ew,
                            int* __restrict__ row32, int* __restrict__ col32,
                            float* __restrict__ deg, int* __restrict__ cnt) {
    int e = blockIdx.x * blockDim.x + threadIdx.x;
    if (e < NE) {
        int r, c;
        if (*flag) { r = buf[e];     c = buf[NE + e]; }
        else       { r = buf[2 * e]; c = buf[2 * NE + 2 * e]; }
        row32[e] = r;
        col32[e] = c;
        atomicAdd(&deg[c], ew[e]);
        atomicAdd(&cnt[c], 1);
    }
}

// ---------------- exclusive scan (3 kernels; dinv folded into scan3) --------

__global__ void scan1_k(const int* __restrict__ cnt, int* __restrict__ off,
                        int* __restrict__ bsum) {
    __shared__ int sh[256];
    int tid = threadIdx.x;
    int base = blockIdx.x * 1024 + tid * 4;
    int v[4];
#pragma unroll
    for (int j = 0; j < 4; j++) v[j] = (base + j < NN) ? cnt[base + j] : 0;
    int s = v[0] + v[1] + v[2] + v[3];
    sh[tid] = s;
    __syncthreads();
    for (int d = 1; d < 256; d <<= 1) {
        int add = (tid >= d) ? sh[tid - d] : 0;
        __syncthreads();
        sh[tid] += add;
        __syncthreads();
    }
    int run = sh[tid] - s;
#pragma unroll
    for (int j = 0; j < 4; j++) {
        if (base + j < NN) off[base + j] = run;
        run += v[j];
    }
    if (tid == 255) bsum[blockIdx.x] = sh[255];
}

__global__ void scan2_k(int* __restrict__ bsum, int* __restrict__ off, int nblk) {
    __shared__ int sh[128];
    int tid = threadIdx.x;
    int s = (tid < nblk) ? bsum[tid] : 0;
    sh[tid] = s;
    __syncthreads();
    for (int d = 1; d < 128; d <<= 1) {
        int add = (tid >= d) ? sh[tid - d] : 0;
        __syncthreads();
        sh[tid] += add;
        __syncthreads();
    }
    if (tid < nblk) bsum[tid] = sh[tid] - s;
    if (tid == 0) off[NN] = NE;
}

// off += block offset; cursor = off; dinv = rsqrt(deg)
__global__ void scan3_dinv_k(int* __restrict__ off, const int* __restrict__ bsum,
                             int* __restrict__ cursor,
                             const float* __restrict__ deg,
                             float* __restrict__ dinv) {
    int i = blockIdx.x * blockDim.x + threadIdx.x;
    if (i < NN) {
        int o = off[i] + bsum[i >> 10];
        off[i] = o;
        cursor[i] = o;
        float d = deg[i];
        dinv[i] = (d > 0.0f) ? rsqrtf(d) : 0.0f;
    }
}

// scatter edges into packed CSR, computing norm inline.
__global__ void scatter_k(const int* __restrict__ row32, const int* __restrict__ col32,
                          const float* __restrict__ ew, const float* __restrict__ dinv,
                          int* __restrict__ cursor, int2* __restrict__ csr) {
    int e = blockIdx.x * blockDim.x + threadIdx.x;
    if (e < NE) {
        int r = row32[e];
        int c = col32[e];
        float w = dinv[r] * ew[e] * dinv[c];
        int pos = atomicAdd(&cursor[c], 1);
        int2 p; p.x = r; p.y = __float_as_int(w);
        csr[pos] = p;
    }
}

// ---------------- TF32 GEMM: [N,K] @ [K,64] -> [N,64] ----------------
// Block 256 thr (8 warps). Tile 128x64. Warp computes 16 rows x 64 cols via
// 8x mma.m16n8k8 per k8-step. Inputs rounded to tf32 at staging; fp32 accum.

template <int K, bool RELU, bool BIAS>
__global__ void gemm_tf32(const float* __restrict__ X, const float* __restrict__ W,
                          const float* __restrict__ bias, float* __restrict__ Y,
                          int N) {
    constexpr int KC = 32;
    __shared__ float Xs[128][36];   // pad 4: conflict-free frag loads
    __shared__ float Ws[32][68];    // pad 4
    const int tid = threadIdx.x;
    const int wid = tid >> 5;
    const int lane = tid & 31;
    const int g = lane >> 2;        // 0..7
    const int tg = lane & 3;        // 0..3
    const int row0 = blockIdx.x * 128;
    const int wm = wid * 16;

    float c[8][4];
#pragma unroll
    for (int nt = 0; nt < 8; nt++)
#pragma unroll
        for (int j = 0; j < 4; j++) c[nt][j] = 0.0f;

    for (int kc = 0; kc < K; kc += KC) {
#pragma unroll
        for (int i = 0; i < 4; i++) {
            int idx = i * 256 + tid;     // 1024 float4
            int r = idx >> 3;            // 8 float4 per row
            int k4 = idx & 7;
            float4 v = make_float4(0.f, 0.f, 0.f, 0.f);
            int rg = row0 + r;
            if (rg < N)
                v = *(const float4*)&X[(size_t)rg * K + kc + k4 * 4];
            Xs[r][k4 * 4 + 0] = to_tf32(v.x);
            Xs[r][k4 * 4 + 1] = to_tf32(v.y);
            Xs[r][k4 * 4 + 2] = to_tf32(v.z);
            Xs[r][k4 * 4 + 3] = to_tf32(v.w);
        }
#pragma unroll
        for (int i = 0; i < 2; i++) {
            int idx = i * 256 + tid;     // 512 float4
            int k = idx >> 4;
            int c4 = idx & 15;
            float4 v = *(const float4*)&W[(size_t)(kc + k) * 64 + c4 * 4];
            Ws[k][c4 * 4 + 0] = to_tf32(v.x);
            Ws[k][c4 * 4 + 1] = to_tf32(v.y);
            Ws[k][c4 * 4 + 2] = to_tf32(v.z);
            Ws[k][c4 * 4 + 3] = to_tf32(v.w);
        }
        __syncthreads();

#pragma unroll
        for (int k8 = 0; k8 < KC; k8 += 8) {
            uint32_t a0 = __float_as_uint(Xs[wm + g][k8 + tg]);
            uint32_t a1 = __float_as_uint(Xs[wm + g + 8][k8 + tg]);
            uint32_t a2 = __float_as_uint(Xs[wm + g][k8 + tg + 4]);
            uint32_t a3 = __float_as_uint(Xs[wm + g + 8][k8 + tg + 4]);
#pragma unroll
            for (int nt = 0; nt < 8; nt++) {
                uint32_t b0 = __float_as_uint(Ws[k8 + tg][nt * 8 + g]);
                uint32_t b1 = __float_as_uint(Ws[k8 + tg + 4][nt * 8 + g]);
                asm volatile(
                    "mma.sync.aligned.m16n8k8.row.col.f32.tf32.tf32.f32 "
                    "{%0,%1,%2,%3}, {%4,%5,%6,%7}, {%8,%9}, {%0,%1,%2,%3};"
                    : "+f"(c[nt][0]), "+f"(c[nt][1]), "+f"(c[nt][2]), "+f"(c[nt][3])
                    : "r"(a0), "r"(a1), "r"(a2), "r"(a3), "r"(b0), "r"(b1));
            }
        }
        __syncthreads();
    }

    const int r0 = row0 + wm + g;
    const int r1 = r0 + 8;
#pragma unroll
    for (int nt = 0; nt < 8; nt++) {
        int n0 = nt * 8 + 2 * tg;
        float bx = 0.f, by = 0.f;
        if (BIAS) { bx = __ldg(&bias[n0]); by = __ldg(&bias[n0 + 1]); }
        float2 v0, v1;
        v0.x = c[nt][0] + bx; v0.y = c[nt][1] + by;
        v1.x = c[nt][2] + bx; v1.y = c[nt][3] + by;
        if (RELU) {
            v0.x = fmaxf(v0.x, 0.f); v0.y = fmaxf(v0.y, 0.f);
            v1.x = fmaxf(v1.x, 0.f); v1.y = fmaxf(v1.y, 0.f);
        }
        if (r0 < N) *(float2*)&Y[(size_t)r0 * 64 + n0] = v0;
        if (r1 < N) *(float2*)&Y[(size_t)r1 * 64 + n0] = v1;
    }
}

// ---------------- final GEMM: [N,64] @ [64,40] + b (fp32) ----------------

__global__ void gemm_final(const float* __restrict__ X, const float* __restrict__ W,
                           const float* __restrict__ bias, float* __restrict__ Y,
                           int N) {
    __shared__ float Xs[64][68];
    __shared__ float Ws[64][40];
    __shared__ float bs[40];
    const int tid = threadIdx.x;
    const int row0 = blockIdx.x * 64;

#pragma unroll
    for (int i = 0; i < 4; i++) {
        int idx = i * 256 + tid;
        int r = idx >> 4;
        int k4 = idx & 15;
        float4 v = make_float4(0.f, 0.f, 0.f, 0.f);
        int rg = row0 + r;
        if (rg < N) v = *(const float4*)&X[(size_t)rg * 64 + k4 * 4];
        *(float4*)&Xs[r][k4 * 4] = v;
    }
    for (int idx = tid; idx < 64 * 40; idx += 256)
        Ws[idx / 40][idx % 40] = W[idx];
    if (tid < 40) bs[tid] = bias[tid];
    __syncthreads();

#pragma unroll
    for (int i = 0; i < 10; i++) {
        int idx = tid + i * 256;
        int r = idx / 40;
        int c = idx % 40;
        float acc = bs[c];
#pragma unroll 16
        for (int k = 0; k < 64; k++) acc += Xs[r][k] * Ws[k][c];
        int rg = row0 + r;
        if (rg < N) Y[(size_t)rg * 40 + c] = acc;
    }
}

// ---------------- fused CSR aggregation + bias + relu ----------------
// Warp per node, lane = 2 cols (float2). 8-way unroll for MLP=8.

__global__ void spmm_csr_k(const int* __restrict__ off,
                           const int2* __restrict__ csr,
                           const float* __restrict__ t,
                           const float* __restrict__ dinv,
                           const float* __restrict__ bias,
                           float* __restrict__ hout) {
    int n = blockIdx.x * 8 + (threadIdx.x >> 5);
    if (n >= NN) return;
    int lane = threadIdx.x & 31;
    const float2* t2 = (const float2*)t;

    float di = __ldg(&dinv[n]);
    float sw = di * di;
    float2 self = t2[(size_t)n * 32 + lane];
    float accx = self.x * sw;
    float accy = self.y * sw;

    int e = __ldg(&off[n]);
    const int end = __ldg(&off[n + 1]);

    for (; e + 8 <= end; e += 8) {
        int2 p[8];
#pragma unroll
        for (int j = 0; j < 8; j++) p[j] = __ldg(&csr[e + j]);
        float2 v[8];
#pragma unroll
        for (int j = 0; j < 8; j++) v[j] = t2[(size_t)p[j].x * 32 + lane];
#pragma unroll
        for (int j = 0; j < 8; j++) {
            float w = __int_as_float(p[j].y);
            accx += w * v[j].x;
            accy += w * v[j].y;
        }
    }
    if (e + 4 <= end) {
        int2 p[4];
#pragma unroll
        for (int j = 0; j < 4; j++) p[j] = __ldg(&csr[e + j]);
        float2 v[4];
#pragma unroll
        for (int j = 0; j < 4; j++) v[j] = t2[(size_t)p[j].x * 32 + lane];
#pragma unroll
        for (int j = 0; j < 4; j++) {
            float w = __int_as_float(p[j].y);
            accx += w * v[j].x;
            accy += w * v[j].y;
        }
        e += 4;
    }
    for (; e < end; e++) {
        int2 p = __ldg(&csr[e]);
        float w = __int_as_float(p.y);
        float2 v = t2[(size_t)p.x * 32 + lane];
        accx += w * v.x;
        accy += w * v.y;
    }

    float2 bv = ((const float2*)bias)[lane];
    accx = fmaxf(accx + bv.x, 0.0f);
    accy = fmaxf(accy + bv.y, 0.0f);
    float2 o; o.x = accx; o.y = accy;
    ((float2*)hout)[(size_t)n * 32 + lane] = o;
}

// ---------------- launch ----------------

extern "C" void kernel_launch(void* const* d_in, const int* in_sizes, int n_in,
                              void* d_out, int out_size) {
    const float* x   = (const float*)d_in[0];
    const int*   ei  = (const int*)d_in[1];
    const float* ew  = (const float*)d_in[2];
    const float* W1  = (const float*)d_in[3];
    const float* b1  = (const float*)d_in[4];
    const float* Wc1 = (const float*)d_in[5];
    const float* bc1 = (const float*)d_in[6];
    const float* Wc2 = (const float*)d_in[7];
    const float* bc2 = (const float*)d_in[8];
    const float* W2  = (const float*)d_in[9];
    const float* b2  = (const float*)d_in[10];
    float* out = (float*)d_out;

    float *h, *t, *deg, *dinv;
    int *r32, *c32, *flag, *cnt, *off, *cursor, *bsum;
    int2 *csr;
    cudaGetSymbolAddress((void**)&h,     g_h);
    cudaGetSymbolAddress((void**)&t,     g_t);
    cudaGetSymbolAddress((void**)&deg,   g_deg);
    cudaGetSymbolAddress((void**)&dinv,  g_dinv);
    cudaGetSymbolAddress((void**)&r32,   g_row32);
    cudaGetSymbolAddress((void**)&c32,   g_col32);
    cudaGetSymbolAddress((void**)&flag,  g_is32);
    cudaGetSymbolAddress((void**)&cnt,   g_cnt);
    cudaGetSymbolAddress((void**)&off,   g_off);
    cudaGetSymbolAddress((void**)&cursor,g_cursor);
    cudaGetSymbolAddress((void**)&bsum,  g_bsum);
    cudaGetSymbolAddress((void**)&csr,   g_csr);

    const int TB = 256;
    const int mma_blocks = (NN + 127) / 128;       // 782
    const int fin_blocks = (NN + 63) / 64;         // 1563
    const int nscan = (NN + 1023) / 1024;          // 98
    const int spmm_blocks = (NN + 7) / 8;          // 12500

    // 1-3: init, detect, convert+count
    init_k<<<(NN + TB - 1) / TB, TB>>>(deg, cnt, flag);
    detect_k<<<256, 256>>>(ei, flag);
    cvt_count_k<<<(NE + TB - 1) / TB, TB>>>(ei, flag, ew, r32, c32, deg, cnt);

    // 4: h = relu(x @ W1 + b1)  — independent of CSR build; sits in the
    // ncu-captured launch slot for profiling.
    gemm_tf32<FIN, true, true><<<mma_blocks, TB>>>(x, W1, b1, h, NN);

    // 5-8: CSR build
    scan1_k<<<nscan, 256>>>(cnt, off, bsum);
    scan2_k<<<1, 128>>>(bsum, off, nscan);
    scan3_dinv_k<<<(NN + TB - 1) / TB, TB>>>(off, bsum, cursor, deg, dinv);
    scatter_k<<<(NE + TB - 1) / TB, TB>>>(r32, c32, ew, dinv, cursor, csr);

    // conv1
    gemm_tf32<HID, false, false><<<mma_blocks, TB>>>(h, Wc1, nullptr, t, NN);
    spmm_csr_k<<<spmm_blocks, TB>>>(off, csr, t, dinv, bc1, h);

    // conv2
    gemm_tf32<HID, false, false><<<mma_blocks, TB>>>(h, Wc2, nullptr, t, NN);
    spmm_csr_k<<<spmm_blocks, TB>>>(off, csr, t, dinv, bc2, h);

    // out = h @ W2 + b2
    gemm_final<<<fin_blocks, TB>>>(h, W2, b2, out, NN);
}

// round 11
// speedup vs baseline: 3.2867x; 1.1299x over previous
#include <cuda_runtime.h>
#include <cuda_bf16.h>
#include <cuda_fp16.h>
#include <cstdint>

// ---------------------------------------------------------------------------
// GCN forward. Round 10: cp.async double-buffered tf32 GEMM (was LDS-bound,
// tensor=16%, L1=55%), fp16 storage for t (halves spmm gather traffic),
// vectorized index conversion.
//
// Target facts learned:
//  - v4/v2 fp32 atomics trap. Scalar atomicAdd only. (Plain vector loads OK.)
//  - edge_index encoding ambiguous (int32 vs int64) -> detected on device.
//  - ~3us per-launch floor: fewer, fatter kernels.
// ---------------------------------------------------------------------------

#define NN 100000
#define NE 1600000
#define FIN 256
#define HID 64
#define NCLS 40

// Scratch (__device__ globals; no allocations allowed)
__device__ float  g_h[(size_t)NN * HID];
__device__ __half g_t[(size_t)NN * HID];
__device__ float  g_deg[NN];
__device__ float  g_dinv[NN];
__device__ int    g_row32[NE];
__device__ int    g_col32[NE];
__device__ int    g_cnt[NN];
__device__ int    g_off[NN + 1];
__device__ int    g_cursor[NN];
__device__ int    g_bsum[128];
__device__ int2   g_csr[NE];        // packed {src, float_as_int(w)}
__device__ int    g_is32;

__device__ __forceinline__ uint32_t tf32_bits(float x) {
    uint32_t u;
    asm("cvt.rna.tf32.f32 %0, %1;" : "=r"(u) : "f"(x));
    return u;
}
__device__ __forceinline__ float to_tf32(float x) {
    return __uint_as_float(tf32_bits(x));
}
__device__ __forceinline__ void cp_async16(uint32_t dst, const void* src, bool valid) {
    int sz = valid ? 16 : 0;
    asm volatile("cp.async.cg.shared.global [%0], [%1], 16, %2;"
                 :: "r"(dst), "l"(src), "r"(sz));
}
#define CP_COMMIT() asm volatile("cp.async.commit_group;")
#define CP_WAIT(n)  asm volatile("cp.async.wait_group %0;" :: "n"(n))

// ---------------- init + dtype detection + conversion/count ----------------

__global__ void init_k(float* __restrict__ deg, int* __restrict__ cnt,
                       int* __restrict__ flag) {
    int i = blockIdx.x * blockDim.x + threadIdx.x;
    if (i < NN) { deg[i] = 1.0f; cnt[i] = 0; }
    if (i == 0) *flag = 0;
}

// int64 little-endian with small values => odd 32-bit words all zero.
__global__ void detect_k(const int* __restrict__ buf, int* __restrict__ flag) {
    int i = blockIdx.x * blockDim.x + threadIdx.x;   // 65536 samples
    if (buf[2 * i + 1] != 0) atomicOr(flag, 1);
}

__global__ void cvt_count_k(const int* __restrict__ buf,
                            const int* __restrict__ flag,
                            const float* __restrict__ ew,
                            int* __restrict__ row32, int* __restrict__ col32,
                            float* __restrict__ deg, int* __restrict__ cnt) {
    int e = blockIdx.x * blockDim.x + threadIdx.x;
    if (e < NE) {
        int r, c;
        if (*flag) {
            r = buf[e]; c = buf[NE + e];
        } else {
            const int2* b2 = (const int2*)buf;
            r = b2[e].x;            // low word of int64 rows[e]
            c = b2[NE + e].x;       // low word of int64 cols[e]
        }
        row32[e] = r;
        col32[e] = c;
        atomicAdd(&deg[c], ew[e]);
        atomicAdd(&cnt[c], 1);
    }
}

// ---------------- exclusive scan (3 kernels; dinv folded into scan3) --------

__global__ void scan1_k(const int* __restrict__ cnt, int* __restrict__ off,
                        int* __restrict__ bsum) {
    __shared__ int sh[256];
    int tid = threadIdx.x;
    int base = blockIdx.x * 1024 + tid * 4;
    int v[4];
#pragma unroll
    for (int j = 0; j < 4; j++) v[j] = (base + j < NN) ? cnt[base + j] : 0;
    int s = v[0] + v[1] + v[2] + v[3];
    sh[tid] = s;
    __syncthreads();
    for (int d = 1; d < 256; d <<= 1) {
        int add = (tid >= d) ? sh[tid - d] : 0;
        __syncthreads();
        sh[tid] += add;
        __syncthreads();
    }
    int run = sh[tid] - s;
#pragma unroll
    for (int j = 0; j < 4; j++) {
        if (base + j < NN) off[base + j] = run;
        run += v[j];
    }
    if (tid == 255) bsum[blockIdx.x] = sh[255];
}

__global__ void scan2_k(int* __restrict__ bsum, int* __restrict__ off, int nblk) {
    __shared__ int sh[128];
    int tid = threadIdx.x;
    int s = (tid < nblk) ? bsum[tid] : 0;
    sh[tid] = s;
    __syncthreads();
    for (int d = 1; d < 128; d <<= 1) {
        int add = (tid >= d) ? sh[tid - d] : 0;
        __syncthreads();
        sh[tid] += add;
        __syncthreads();
    }
    if (tid < nblk) bsum[tid] = sh[tid] - s;
    if (tid == 0) off[NN] = NE;
}

__global__ void scan3_dinv_k(int* __restrict__ off, const int* __restrict__ bsum,
                             int* __restrict__ cursor,
                             const float* __restrict__ deg,
                             float* __restrict__ dinv) {
    int i = blockIdx.x * blockDim.x + threadIdx.x;
    if (i < NN) {
        int o = off[i] + bsum[i >> 10];
        off[i] = o;
        cursor[i] = o;
        float d = deg[i];
        dinv[i] = (d > 0.0f) ? rsqrtf(d) : 0.0f;
    }
}

__global__ void scatter_k(const int* __restrict__ row32, const int* __restrict__ col32,
                          const float* __restrict__ ew, const float* __restrict__ dinv,
                          int* __restrict__ cursor, int2* __restrict__ csr) {
    int e = blockIdx.x * blockDim.x + threadIdx.x;
    if (e < NE) {
        int r = row32[e];
        int c = col32[e];
        float w = dinv[r] * ew[e] * dinv[c];
        int pos = atomicAdd(&cursor[c], 1);
        int2 p; p.x = r; p.y = __float_as_int(w);
        csr[pos] = p;
    }
}

// ---------------- TF32 GEMM: [N,K] @ [K,64] -> [N,64] ----------------
// Block 256 thr (8 warps), tile 128x64, KC=32. Two-stage cp.async pipeline on
// X; W register-staged into a single conflict-free (pad 72) smem buffer.
// A frags rounded to tf32 at frag load, W at staging. fp32 accumulate.
// HOUT: write output as __half (for t before the spmm gather).

template <int K, bool RELU, bool BIAS, bool HOUT>
__global__ void gemm_tf32(const float* __restrict__ X, const float* __restrict__ W,
                          const float* __restrict__ bias, void* __restrict__ Yv,
                          int N) {
    constexpr int KC = 32;
    constexpr int NK = K / KC;
    __shared__ float Xs[2][128][36];   // 36*4=144B rows (16B aligned); frag conflict-free
    __shared__ float Ws[32][72];       // 72: tg*8+g covers 32 banks, conflict-free

    const int tid = threadIdx.x;
    const int wid = tid >> 5;
    const int lane = tid & 31;
    const int g = lane >> 2;
    const int tg = lane & 3;
    const int row0 = blockIdx.x * 128;
    const int wm = wid * 16;

    uint32_t xs_base;
    {
        void* p = (void*)&Xs[0][0][0];
        xs_base = (uint32_t)__cvta_generic_to_shared(p);
    }

    float c[8][4];
#pragma unroll
    for (int nt = 0; nt < 8; nt++)
#pragma unroll
        for (int j = 0; j < 4; j++) c[nt][j] = 0.0f;

    float4 wr[2];

    // stage X chunk kc into buffer buf via cp.async (ZFILL for OOB rows)
    auto stage_x = [&](int buf, int kc) {
#pragma unroll
        for (int i = 0; i < 4; i++) {
            int idx = i * 256 + tid;      // 1024 float4
            int r = idx >> 3;             // 8 float4 per row
            int k4 = idx & 7;
            int rg = row0 + r;
            const float* src = &X[(size_t)rg * K + kc + k4 * 4];
            uint32_t dst = xs_base + (uint32_t)(((buf * 128 + r) * 36 + k4 * 4) * 4);
            cp_async16(dst, src, rg < N);
        }
    };
    auto ldg_w = [&](int kc) {
#pragma unroll
        for (int i = 0; i < 2; i++) {
            int idx = i * 256 + tid;      // 512 float4
            int k = idx >> 4;
            int c4 = idx & 15;
            wr[i] = *(const float4*)&W[(size_t)(kc + k) * 64 + c4 * 4];
        }
    };
    auto sts_w = [&]() {
#pragma unroll
        for (int i = 0; i < 2; i++) {
            int idx = i * 256 + tid;
            int k = idx >> 4;
            int c4 = idx & 15;
            Ws[k][c4 * 4 + 0] = to_tf32(wr[i].x);
            Ws[k][c4 * 4 + 1] = to_tf32(wr[i].y);
            Ws[k][c4 * 4 + 2] = to_tf32(wr[i].z);
            Ws[k][c4 * 4 + 3] = to_tf32(wr[i].w);
        }
    };

    // prologue
    stage_x(0, 0);
    CP_COMMIT();
    ldg_w(0);
    sts_w();

#pragma unroll
    for (int i = 0; i < NK; i++) {
        if (i + 1 < NK) {
            stage_x((i + 1) & 1, (i + 1) * KC);
            CP_COMMIT();
            ldg_w((i + 1) * KC);
            CP_WAIT(1);
        } else {
            CP_WAIT(0);
        }
        __syncthreads();

        const int buf = i & 1;
#pragma unroll
        for (int k8 = 0; k8 < KC; k8 += 8) {
            uint32_t a0 = tf32_bits(Xs[buf][wm + g][k8 + tg]);
            uint32_t a1 = tf32_bits(Xs[buf][wm + g + 8][k8 + tg]);
            uint32_t a2 = tf32_bits(Xs[buf][wm + g][k8 + tg + 4]);
            uint32_t a3 = tf32_bits(Xs[buf][wm + g + 8][k8 + tg + 4]);
#pragma unroll
            for (int nt = 0; nt < 8; nt++) {
                uint32_t b0 = __float_as_uint(Ws[k8 + tg][nt * 8 + g]);
                uint32_t b1 = __float_as_uint(Ws[k8 + tg + 4][nt * 8 + g]);
                asm volatile(
                    "mma.sync.aligned.m16n8k8.row.col.f32.tf32.tf32.f32 "
                    "{%0,%1,%2,%3}, {%4,%5,%6,%7}, {%8,%9}, {%0,%1,%2,%3};"
                    : "+f"(c[nt][0]), "+f"(c[nt][1]), "+f"(c[nt][2]), "+f"(c[nt][3])
                    : "r"(a0), "r"(a1), "r"(a2), "r"(a3), "r"(b0), "r"(b1));
            }
        }
        __syncthreads();
        if (i + 1 < NK) sts_w();   // Ws for next chunk; visible after next sync
    }

    // Epilogue: thread owns rows (wm+g, wm+g+8), cols nt*8 + 2*tg (+1)
    const int r0 = row0 + wm + g;
    const int r1 = r0 + 8;
#pragma unroll
    for (int nt = 0; nt < 8; nt++) {
        int n0 = nt * 8 + 2 * tg;
        float bx = 0.f, by = 0.f;
        if (BIAS) { bx = __ldg(&bias[n0]); by = __ldg(&bias[n0 + 1]); }
        float2 v0, v1;
        v0.x = c[nt][0] + bx; v0.y = c[nt][1] + by;
        v1.x = c[nt][2] + bx; v1.y = c[nt][3] + by;
        if (RELU) {
            v0.x = fmaxf(v0.x, 0.f); v0.y = fmaxf(v0.y, 0.f);
            v1.x = fmaxf(v1.x, 0.f); v1.y = fmaxf(v1.y, 0.f);
        }
        if (HOUT) {
            __half2* Yh = (__half2*)Yv;
            if (r0 < N) Yh[(size_t)r0 * 32 + n0 / 2] = __floats2half2_rn(v0.x, v0.y);
            if (r1 < N) Yh[(size_t)r1 * 32 + n0 / 2] = __floats2half2_rn(v1.x, v1.y);
        } else {
            float* Yf = (float*)Yv;
            if (r0 < N) *(float2*)&Yf[(size_t)r0 * 64 + n0] = v0;
            if (r1 < N) *(float2*)&Yf[(size_t)r1 * 64 + n0] = v1;
        }
    }
}

// ---------------- final GEMM: [N,64] @ [64,40] + b (fp32) ----------------

__global__ void gemm_final(const float* __restrict__ X, const float* __restrict__ W,
                           const float* __restrict__ bias, float* __restrict__ Y,
                           int N) {
    __shared__ float Xs[64][68];
    __shared__ float Ws[64][40];
    __shared__ float bs[40];
    const int tid = threadIdx.x;
    const int row0 = blockIdx.x * 64;

#pragma unroll
    for (int i = 0; i < 4; i++) {
        int idx = i * 256 + tid;
        int r = idx >> 4;
        int k4 = idx & 15;
        float4 v = make_float4(0.f, 0.f, 0.f, 0.f);
        int rg = row0 + r;
        if (rg < N) v = *(const float4*)&X[(size_t)rg * 64 + k4 * 4];
        *(float4*)&Xs[r][k4 * 4] = v;
    }
    for (int idx = tid; idx < 64 * 40; idx += 256)
        Ws[idx / 40][idx % 40] = W[idx];
    if (tid < 40) bs[tid] = bias[tid];
    __syncthreads();

#pragma unroll
    for (int i = 0; i < 10; i++) {
        int idx = tid + i * 256;
        int r = idx / 40;
        int c = idx % 40;
        float acc = bs[c];
#pragma unroll 16
        for (int k = 0; k < 64; k++) acc += Xs[r][k] * Ws[k][c];
        int rg = row0 + r;
        if (rg < N) Y[(size_t)rg * 40 + c] = acc;
    }
}

// ---------------- fused CSR aggregation + bias + relu ----------------
// Warp per node, lane = 2 cols (__half2 gather, fp32 accumulate).

__global__ void spmm_csr_k(const int* __restrict__ off,
                           const int2* __restrict__ csr,
                           const __half* __restrict__ t,
                           const float* __restrict__ dinv,
                           const float* __restrict__ bias,
                           float* __restrict__ hout) {
    int n = blockIdx.x * 8 + (threadIdx.x >> 5);
    if (n >= NN) return;
    int lane = threadIdx.x & 31;
    const __half2* t2 = (const __half2*)t;

    float di = __ldg(&dinv[n]);
    float sw = di * di;
    float2 self = __half22float2(t2[(size_t)n * 32 + lane]);
    float accx = self.x * sw;
    float accy = self.y * sw;

    int e = __ldg(&off[n]);
    const int end = __ldg(&off[n + 1]);

    for (; e + 8 <= end; e += 8) {
        int2 p[8];
#pragma unroll
        for (int j = 0; j < 8; j++) p[j] = __ldg(&csr[e + j]);
        __half2 v[8];
#pragma unroll
        for (int j = 0; j < 8; j++) v[j] = t2[(size_t)p[j].x * 32 + lane];
#pragma unroll
        for (int j = 0; j < 8; j++) {
            float w = __int_as_float(p[j].y);
            float2 f = __half22float2(v[j]);
            accx += w * f.x;
            accy += w * f.y;
        }
    }
    if (e + 4 <= end) {
        int2 p[4];
#pragma unroll
        for (int j = 0; j < 4; j++) p[j] = __ldg(&csr[e + j]);
        __half2 v[4];
#pragma unroll
        for (int j = 0; j < 4; j++) v[j] = t2[(size_t)p[j].x * 32 + lane];
#pragma unroll
        for (int j = 0; j < 4; j++) {
            float w = __int_as_float(p[j].y);
            float2 f = __half22float2(v[j]);
            accx += w * f.x;
            accy += w * f.y;
        }
        e += 4;
    }
    for (; e < end; e++) {
        int2 p = __ldg(&csr[e]);
        float w = __int_as_float(p.y);
        float2 f = __half22float2(t2[(size_t)p.x * 32 + lane]);
        accx += w * f.x;
        accy += w * f.y;
    }

    float2 bv = ((const float2*)bias)[lane];
    accx = fmaxf(accx + bv.x, 0.0f);
    accy = fmaxf(accy + bv.y, 0.0f);
    float2 o; o.x = accx; o.y = accy;
    ((float2*)hout)[(size_t)n * 32 + lane] = o;
}

// ---------------- launch ----------------

extern "C" void kernel_launch(void* const* d_in, const int* in_sizes, int n_in,
                              void* d_out, int out_size) {
    const float* x   = (const float*)d_in[0];
    const int*   ei  = (const int*)d_in[1];
    const float* ew  = (const float*)d_in[2];
    const float* W1  = (const float*)d_in[3];
    const float* b1  = (const float*)d_in[4];
    const float* Wc1 = (const float*)d_in[5];
    const float* bc1 = (const float*)d_in[6];
    const float* Wc2 = (const float*)d_in[7];
    const float* bc2 = (const float*)d_in[8];
    const float* W2  = (const float*)d_in[9];
    const float* b2  = (const float*)d_in[10];
    float* out = (float*)d_out;

    float *h, *deg, *dinv;
    __half* t;
    int *r32, *c32, *flag, *cnt, *off, *cursor, *bsum;
    int2 *csr;
    cudaGetSymbolAddress((void**)&h,     g_h);
    cudaGetSymbolAddress((void**)&t,     g_t);
    cudaGetSymbolAddress((void**)&deg,   g_deg);
    cudaGetSymbolAddress((void**)&dinv,  g_dinv);
    cudaGetSymbolAddress((void**)&r32,   g_row32);
    cudaGetSymbolAddress((void**)&c32,   g_col32);
    cudaGetSymbolAddress((void**)&flag,  g_is32);
    cudaGetSymbolAddress((void**)&cnt,   g_cnt);
    cudaGetSymbolAddress((void**)&off,   g_off);
    cudaGetSymbolAddress((void**)&cursor,g_cursor);
    cudaGetSymbolAddress((void**)&bsum,  g_bsum);
    cudaGetSymbolAddress((void**)&csr,   g_csr);

    const int TB = 256;
    const int mma_blocks = (NN + 127) / 128;       // 782
    const int fin_blocks = (NN + 63) / 64;         // 1563
    const int nscan = (NN + 1023) / 1024;          // 98
    const int spmm_blocks = (NN + 7) / 8;          // 12500

    // 1-3: init, detect, convert+count
    init_k<<<(NN + TB - 1) / TB, TB>>>(deg, cnt, flag);
    detect_k<<<256, 256>>>(ei, flag);
    cvt_count_k<<<(NE + TB - 1) / TB, TB>>>(ei, flag, ew, r32, c32, deg, cnt);

    // 4: h = relu(x @ W1 + b1) — in the ncu-captured launch slot.
    gemm_tf32<FIN, true, true, false><<<mma_blocks, TB>>>(x, W1, b1, h, NN);

    // 5-8: CSR build
    scan1_k<<<nscan, 256>>>(cnt, off, bsum);
    scan2_k<<<1, 128>>>(bsum, off, nscan);
    scan3_dinv_k<<<(NN + TB - 1) / TB, TB>>>(off, bsum, cursor, deg, dinv);
    scatter_k<<<(NE + TB - 1) / TB, TB>>>(r32, c32, ew, dinv, cursor, csr);

    // conv1: t = h@Wc1 (fp16 out) ; h = relu(S t + bc1)
    gemm_tf32<HID, false, false, true><<<mma_blocks, TB>>>(h, Wc1, nullptr, t, NN);
    spmm_csr_k<<<spmm_blocks, TB>>>(off, csr, t, dinv, bc1, h);

    // conv2
    gemm_tf32<HID, false, false, true><<<mma_blocks, TB>>>(h, Wc2, nullptr, t, NN);
    spmm_csr_k<<<spmm_blocks, TB>>>(off, csr, t, dinv, bc2, h);

    // out = h @ W2 + b2
    gemm_final<<<fin_blocks, TB>>>(h, W2, b2, out, NN);
}

// round 13
// speedup vs baseline: 4.2513x; 1.2935x over previous
#include <cuda_runtime.h>
#include <cuda_bf16.h>
#include <cuda_fp16.h>
#include <cstdint>

// ---------------------------------------------------------------------------
// GCN forward. Round 11: KC=16 tf32 GEMM (smem 46->25KB, occ 32->64%),
// packed 64-bit deg/cnt atomic (halves cvt_count atomics), final GEMM
// tensorized via NOUT template.
//
// Target facts learned:
//  - v4/v2 fp32 atomics trap. Scalar atomicAdd (incl. ull) only.
//  - edge_index encoding ambiguous (int32 vs int64) -> detected on device.
//  - ~3us per-launch floor: fewer, fatter kernels.
// ---------------------------------------------------------------------------

#define NN 100000
#define NE 1600000
#define FIN 256
#define HID 64
#define NCLS 40

// Scratch (__device__ globals; no allocations allowed)
__device__ float  g_h[(size_t)NN * HID];
__device__ __half g_t[(size_t)NN * HID];
__device__ unsigned long long g_pack[NN];  // cnt<<40 | fixed24(sum ew)
__device__ float  g_dinv[NN];
__device__ int    g_row32[NE];
__device__ int    g_col32[NE];
__device__ int    g_off[NN + 1];
__device__ int    g_cursor[NN];
__device__ int    g_bsum[128];
__device__ int2   g_csr[NE];        // packed {src, float_as_int(w)}
__device__ int    g_is32;

__device__ __forceinline__ uint32_t tf32_bits(float x) {
    uint32_t u;
    asm("cvt.rna.tf32.f32 %0, %1;" : "=r"(u) : "f"(x));
    return u;
}
__device__ __forceinline__ float to_tf32(float x) {
    return __uint_as_float(tf32_bits(x));
}
__device__ __forceinline__ void cp_async16(uint32_t dst, const void* src, bool valid) {
    int sz = valid ? 16 : 0;
    asm volatile("cp.async.cg.shared.global [%0], [%1], 16, %2;"
                 :: "r"(dst), "l"(src), "r"(sz));
}
#define CP_COMMIT() asm volatile("cp.async.commit_group;")
#define CP_WAIT(n)  asm volatile("cp.async.wait_group %0;" :: "n"(n))

// ---------------- init + dtype detection + conversion/count ----------------

__global__ void init_k(unsigned long long* __restrict__ pack,
                       int* __restrict__ flag) {
    int i = blockIdx.x * blockDim.x + threadIdx.x;
    if (i < NN) pack[i] = 0ull;
    if (i == 0) *flag = 0;
}

// int64 little-endian with small values => odd 32-bit words all zero.
__global__ void detect_k(const int* __restrict__ buf, int* __restrict__ flag) {
    int i = blockIdx.x * blockDim.x + threadIdx.x;   // 65536 samples
    if (buf[2 * i + 1] != 0) atomicOr(flag, 1);
}

__global__ void cvt_count_k(const int* __restrict__ buf,
                            const int* __restrict__ flag,
                            const float* __restrict__ ew,
                            int* __restrict__ row32, int* __restrict__ col32,
                            unsigned long long* __restrict__ pack) {
    int e = blockIdx.x * blockDim.x + threadIdx.x;
    if (e < NE) {
        int r, c;
        if (*flag) {
            r = buf[e]; c = buf[NE + e];
        } else {
            const int2* b2 = (const int2*)buf;
            r = b2[e].x;
            c = b2[NE + e].x;
        }
        row32[e] = r;
        col32[e] = c;
        // one packed atomic: count in bits [40+), fixed-point ew sum in [0,40)
        unsigned int q = __float2uint_rn(ew[e] * 16777216.0f);   // 2^24
        atomicAdd(&pack[c], (1ull << 40) | (unsigned long long)q);
    }
}

// ---------------- exclusive scan (3 kernels; dinv folded into scan3) --------

__global__ void scan1_k(const unsigned long long* __restrict__ pack,
                        int* __restrict__ off, int* __restrict__ bsum) {
    __shared__ int sh[256];
    int tid = threadIdx.x;
    int base = blockIdx.x * 1024 + tid * 4;
    int v[4];
#pragma unroll
    for (int j = 0; j < 4; j++)
        v[j] = (base + j < NN) ? (int)(pack[base + j] >> 40) : 0;
    int s = v[0] + v[1] + v[2] + v[3];
    sh[tid] = s;
    __syncthreads();
    for (int d = 1; d < 256; d <<= 1) {
        int add = (tid >= d) ? sh[tid - d] : 0;
        __syncthreads();
        sh[tid] += add;
        __syncthreads();
    }
    int run = sh[tid] - s;
#pragma unroll
    for (int j = 0; j < 4; j++) {
        if (base + j < NN) off[base + j] = run;
        run += v[j];
    }
    if (tid == 255) bsum[blockIdx.x] = sh[255];
}

__global__ void scan2_k(int* __restrict__ bsum, int* __restrict__ off, int nblk) {
    __shared__ int sh[128];
    int tid = threadIdx.x;
    int s = (tid < nblk) ? bsum[tid] : 0;
    sh[tid] = s;
    __syncthreads();
    for (int d = 1; d < 128; d <<= 1) {
        int add = (tid >= d) ? sh[tid - d] : 0;
        __syncthreads();
        sh[tid] += add;
        __syncthreads();
    }
    if (tid < nblk) bsum[tid] = sh[tid] - s;
    if (tid == 0) off[NN] = NE;
}

__global__ void scan3_dinv_k(int* __restrict__ off, const int* __restrict__ bsum,
                             int* __restrict__ cursor,
                             const unsigned long long* __restrict__ pack,
                             float* __restrict__ dinv) {
    int i = blockIdx.x * blockDim.x + threadIdx.x;
    if (i < NN) {
        int o = off[i] + bsum[i >> 10];
        off[i] = o;
        cursor[i] = o;
        float d = 1.0f + (float)(double)(pack[i] & 0xFFFFFFFFFFull) * (1.0f / 16777216.0f);
        dinv[i] = rsqrtf(d);   // d >= 1 always
    }
}

__global__ void scatter_k(const int* __restrict__ row32, const int* __restrict__ col32,
                          const float* __restrict__ ew, const float* __restrict__ dinv,
                          int* __restrict__ cursor, int2* __restrict__ csr) {
    int e = blockIdx.x * blockDim.x + threadIdx.x;
    if (e < NE) {
        int r = row32[e];
        int c = col32[e];
        float w = dinv[r] * ew[e] * dinv[c];
        int pos = atomicAdd(&cursor[c], 1);
        int2 p; p.x = r; p.y = __float_as_int(w);
        csr[pos] = p;
    }
}

// ---------------- TF32 GEMM: [N,K] @ [K,NOUT<=64] -> [N,NOUT] -------------
// Block 256 thr (8 warps), tile 128x64, KC=16 (smem ~25KB -> 4 blocks/SM).
// Two-stage cp.async pipeline on X; W register-staged (zero-padded to 64
// cols when NOUT<64). fp32 accumulate. HOUT: emit __half.

template <int K, int NOUT, bool RELU, bool BIAS, bool HOUT>
__global__ void gemm_tf32(const float* __restrict__ X, const float* __restrict__ W,
                          const float* __restrict__ bias, void* __restrict__ Yv,
                          int N) {
    constexpr int KC = 16;
    constexpr int NK = K / KC;
    constexpr int NV4 = NOUT / 4;      // float4 per W row
    __shared__ float Xs[2][128][20];   // pad 20: conflict-free (20g+tg covers 32 banks)
    __shared__ float Ws[16][72];       // pad 72: tg*8+g conflict-free

    const int tid = threadIdx.x;
    const int wid = tid >> 5;
    const int lane = tid & 31;
    const int g = lane >> 2;
    const int tg = lane & 3;
    const int row0 = blockIdx.x * 128;
    const int wm = wid * 16;

    uint32_t xs_base = (uint32_t)__cvta_generic_to_shared((void*)&Xs[0][0][0]);

    float c[8][4];
#pragma unroll
    for (int nt = 0; nt < 8; nt++)
#pragma unroll
        for (int j = 0; j < 4; j++) c[nt][j] = 0.0f;

    float4 wr;

    auto stage_x = [&](int buf, int kc) {
#pragma unroll
        for (int i = 0; i < 2; i++) {
            int idx = i * 256 + tid;      // 512 float4
            int r = idx >> 2;             // 4 float4 per row
            int k4 = idx & 3;
            int rg = row0 + r;
            const float* src = &X[(size_t)rg * K + kc + k4 * 4];
            uint32_t dst = xs_base + (uint32_t)(((buf * 128 + r) * 20 + k4 * 4) * 4);
            cp_async16(dst, src, rg < N);
        }
    };
    auto ldg_w = [&](int kc) {
        int k = tid >> 4;                 // 0..15
        int c4 = tid & 15;                // 0..15
        if (c4 < NV4)
            wr = *(const float4*)&W[(size_t)(kc + k) * NOUT + c4 * 4];
        else
            wr = make_float4(0.f, 0.f, 0.f, 0.f);
    };
    auto sts_w = [&]() {
        int k = tid >> 4;
        int c4 = tid & 15;
        Ws[k][c4 * 4 + 0] = to_tf32(wr.x);
        Ws[k][c4 * 4 + 1] = to_tf32(wr.y);
        Ws[k][c4 * 4 + 2] = to_tf32(wr.z);
        Ws[k][c4 * 4 + 3] = to_tf32(wr.w);
    };

    // prologue
    stage_x(0, 0);
    CP_COMMIT();
    ldg_w(0);
    sts_w();

#pragma unroll 2
    for (int i = 0; i < NK; i++) {
        if (i + 1 < NK) {
            stage_x((i + 1) & 1, (i + 1) * KC);
            CP_COMMIT();
            ldg_w((i + 1) * KC);
            CP_WAIT(1);
        } else {
            CP_WAIT(0);
        }
        __syncthreads();

        const int buf = i & 1;
#pragma unroll
        for (int k8 = 0; k8 < KC; k8 += 8) {
            uint32_t a0 = tf32_bits(Xs[buf][wm + g][k8 + tg]);
            uint32_t a1 = tf32_bits(Xs[buf][wm + g + 8][k8 + tg]);
            uint32_t a2 = tf32_bits(Xs[buf][wm + g][k8 + tg + 4]);
            uint32_t a3 = tf32_bits(Xs[buf][wm + g + 8][k8 + tg + 4]);
#pragma unroll
            for (int nt = 0; nt < 8; nt++) {
                uint32_t b0 = __float_as_uint(Ws[k8 + tg][nt * 8 + g]);
                uint32_t b1 = __float_as_uint(Ws[k8 + tg + 4][nt * 8 + g]);
                asm volatile(
                    "mma.sync.aligned.m16n8k8.row.col.f32.tf32.tf32.f32 "
                    "{%0,%1,%2,%3}, {%4,%5,%6,%7}, {%8,%9}, {%0,%1,%2,%3};"
                    : "+f"(c[nt][0]), "+f"(c[nt][1]), "+f"(c[nt][2]), "+f"(c[nt][3])
                    : "r"(a0), "r"(a1), "r"(a2), "r"(a3), "r"(b0), "r"(b1));
            }
        }
        __syncthreads();
        if (i + 1 < NK) sts_w();   // Ws for next chunk; visible after next sync
    }

    // Epilogue: thread owns rows (wm+g, wm+g+8), cols nt*8 + 2*tg (+1)
    const int r0 = row0 + wm + g;
    const int r1 = r0 + 8;
#pragma unroll
    for (int nt = 0; nt < 8; nt++) {
        int n0 = nt * 8 + 2 * tg;
        if (n0 >= NOUT) continue;         // padded cols (NOUT<64)
        float bx = 0.f, by = 0.f;
        if (BIAS) { bx = __ldg(&bias[n0]); by = __ldg(&bias[n0 + 1]); }
        float2 v0, v1;
        v0.x = c[nt][0] + bx; v0.y = c[nt][1] + by;
        v1.x = c[nt][2] + bx; v1.y = c[nt][3] + by;
        if (RELU) {
            v0.x = fmaxf(v0.x, 0.f); v0.y = fmaxf(v0.y, 0.f);
            v1.x = fmaxf(v1.x, 0.f); v1.y = fmaxf(v1.y, 0.f);
        }
        if (HOUT) {
            __half2* Yh = (__half2*)Yv;
            if (r0 < N) Yh[((size_t)r0 * NOUT + n0) / 2] = __floats2half2_rn(v0.x, v0.y);
            if (r1 < N) Yh[((size_t)r1 * NOUT + n0) / 2] = __floats2half2_rn(v1.x, v1.y);
        } else {
            float* Yf = (float*)Yv;
            if (r0 < N) *(float2*)&Yf[(size_t)r0 * NOUT + n0] = v0;
            if (r1 < N) *(float2*)&Yf[(size_t)r1 * NOUT + n0] = v1;
        }
    }
}

// ---------------- fused CSR aggregation + bias + relu ----------------
// Warp per node, lane = 2 cols (__half2 gather, fp32 accumulate).

__global__ void spmm_csr_k(const int* __restrict__ off,
                           const int2* __restrict__ csr,
                           const __half* __restrict__ t,
                           const float* __restrict__ dinv,
                           const float* __restrict__ bias,
                           float* __restrict__ hout) {
    int n = blockIdx.x * 8 + (threadIdx.x >> 5);
    if (n >= NN) return;
    int lane = threadIdx.x & 31;
    const __half2* t2 = (const __half2*)t;

    float di = __ldg(&dinv[n]);
    float sw = di * di;
    float2 self = __half22float2(t2[(size_t)n * 32 + lane]);
    float accx = self.x * sw;
    float accy = self.y * sw;

    int e = __ldg(&off[n]);
    const int end = __ldg(&off[n + 1]);

    for (; e + 8 <= end; e += 8) {
        int2 p[8];
#pragma unroll
        for (int j = 0; j < 8; j++) p[j] = __ldg(&csr[e + j]);
        __half2 v[8];
#pragma unroll
        for (int j = 0; j < 8; j++) v[j] = t2[(size_t)p[j].x * 32 + lane];
#pragma unroll
        for (int j = 0; j < 8; j++) {
            float w = __int_as_float(p[j].y);
            float2 f = __half22float2(v[j]);
            accx += w * f.x;
            accy += w * f.y;
        }
    }
    if (e + 4 <= end) {
        int2 p[4];
#pragma unroll
        for (int j = 0; j < 4; j++) p[j] = __ldg(&csr[e + j]);
        __half2 v[4];
#pragma unroll
        for (int j = 0; j < 4; j++) v[j] = t2[(size_t)p[j].x * 32 + lane];
#pragma unroll
        for (int j = 0; j < 4; j++) {
            float w = __int_as_float(p[j].y);
            float2 f = __half22float2(v[j]);
            accx += w * f.x;
            accy += w * f.y;
        }
        e += 4;
    }
    for (; e < end; e++) {
        int2 p = __ldg(&csr[e]);
        float w = __int_as_float(p.y);
        float2 f = __half22float2(t2[(size_t)p.x * 32 + lane]);
        accx += w * f.x;
        accy += w * f.y;
    }

    float2 bv = ((const float2*)bias)[lane];
    accx = fmaxf(accx + bv.x, 0.0f);
    accy = fmaxf(accy + bv.y, 0.0f);
    float2 o; o.x = accx; o.y = accy;
    ((float2*)hout)[(size_t)n * 32 + lane] = o;
}

// ---------------- launch ----------------

extern "C" void kernel_launch(void* const* d_in, const int* in_sizes, int n_in,
                              void* d_out, int out_size) {
    const float* x   = (const float*)d_in[0];
    const int*   ei  = (const int*)d_in[1];
    const float* ew  = (const float*)d_in[2];
    const float* W1  = (const float*)d_in[3];
    const float* b1  = (const float*)d_in[4];
    const float* Wc1 = (const float*)d_in[5];
    const float* bc1 = (const float*)d_in[6];
    const float* Wc2 = (const float*)d_in[7];
    const float* bc2 = (const float*)d_in[8];
    const float* W2  = (const float*)d_in[9];
    const float* b2  = (const float*)d_in[10];
    float* out = (float*)d_out;

    float *h, *dinv;
    __half* t;
    unsigned long long* pack;
    int *r32, *c32, *flag, *off, *cursor, *bsum;
    int2 *csr;
    cudaGetSymbolAddress((void**)&h,     g_h);
    cudaGetSymbolAddress((void**)&t,     g_t);
    cudaGetSymbolAddress((void**)&pack,  g_pack);
    cudaGetSymbolAddress((void**)&dinv,  g_dinv);
    cudaGetSymbolAddress((void**)&r32,   g_row32);
    cudaGetSymbolAddress((void**)&c32,   g_col32);
    cudaGetSymbolAddress((void**)&flag,  g_is32);
    cudaGetSymbolAddress((void**)&off,   g_off);
    cudaGetSymbolAddress((void**)&cursor,g_cursor);
    cudaGetSymbolAddress((void**)&bsum,  g_bsum);
    cudaGetSymbolAddress((void**)&csr,   g_csr);

    const int TB = 256;
    const int mma_blocks = (NN + 127) / 128;       // 782
    const int nscan = (NN + 1023) / 1024;          // 98
    const int spmm_blocks = (NN + 7) / 8;          // 12500

    // 1-3: init, detect, convert+count
    init_k<<<(NN + TB - 1) / TB, TB>>>(pack, flag);
    detect_k<<<256, 256>>>(ei, flag);
    cvt_count_k<<<(NE + TB - 1) / TB, TB>>>(ei, flag, ew, r32, c32, pack);

    // 4: h = relu(x @ W1 + b1) — ncu-captured launch slot.
    gemm_tf32<FIN, HID, true, true, false><<<mma_blocks, TB>>>(x, W1, b1, h, NN);

    // 5-8: CSR build
    scan1_k<<<nscan, 256>>>(pack, off, bsum);
    scan2_k<<<1, 128>>>(bsum, off, nscan);
    scan3_dinv_k<<<(NN + TB - 1) / TB, TB>>>(off, bsum, cursor, pack, dinv);
    scatter_k<<<(NE + TB - 1) / TB, TB>>>(r32, c32, ew, dinv, cursor, csr);

    // conv1: t = h@Wc1 (fp16 out) ; h = relu(S t + bc1)
    gemm_tf32<HID, HID, false, false, true><<<mma_blocks, TB>>>(h, Wc1, nullptr, t, NN);
    spmm_csr_k<<<spmm_blocks, TB>>>(off, csr, t, dinv, bc1, h);

    // conv2
    gemm_tf32<HID, HID, false, false, true><<<mma_blocks, TB>>>(h, Wc2, nullptr, t, NN);
    spmm_csr_k<<<spmm_blocks, TB>>>(off, csr, t, dinv, bc2, h);

    // out = h @ W2 + b2  (tf32, NOUT=40)
    gemm_tf32<HID, NCLS, false, true, false><<<mma_blocks, TB>>>(h, W2, b2, out, NN);
}